// round 2
// baseline (speedup 1.0000x reference)
#include <cuda_runtime.h>
#include <cstdint>

typedef unsigned long long ull;

// ---------------- Problem constants ----------------
#define A_DIM 512
#define V_DIM 768
#define L_DIM 1024
#define H_DIM 512
#define BB    16
#define SS    2048
#define ROWS  (BB * SS)        // 32768
#define G4    (4 * H_DIM)      // 2048
#define CATD  (A_DIM + H_DIM + H_DIM)  // wrong name, real: 1536
#define CAT_K 1536

// ---------------- Scratch (device globals; no allocation allowed) ----------------
__device__ float g_cat[(size_t)ROWS * CAT_K];   // [rows,1536] : a|v|l concat
__device__ float g_ctx[(size_t)ROWS * H_DIM];   // context
__device__ float g_fus[(size_t)ROWS * H_DIM];   // fusion (LSTM input)
__device__ float g_xg [(size_t)ROWS * G4];      // fusion @ Wih^T + (bih+bhh)
__device__ float g_hbuf[2 * BB * H_DIM];        // double-buffered recurrent h
__device__ float g_bsum[G4];                    // bih + bhh
__device__ unsigned int g_ctr;                  // LSTM step sync counter

// ---------------- f32x2 packed helpers ----------------
__device__ __forceinline__ ull ffma2(ull a, ull b, ull c) {
    asm("fma.rn.f32x2 %0, %1, %2, %0;" : "+l"(c) : "l"(a), "l"(b));
    return c;
}
__device__ __forceinline__ ull pack2(float x, float y) {
    ull r; asm("mov.b64 %0, {%1, %2};" : "=l"(r) : "f"(x), "f"(y)); return r;
}
__device__ __forceinline__ void unpack2(ull v, float& x, float& y) {
    asm("mov.b64 {%0, %1}, %2;" : "=f"(x), "=f"(y) : "l"(v));
}
__device__ __forceinline__ float sigmf(float x) {
    return 1.0f / (1.0f + __expf(-x));
}

// ---------------- Init: reset counter + fold biases ----------------
__global__ void init_kernel(const float* __restrict__ bih,
                            const float* __restrict__ bhh) {
    int i = blockIdx.x * blockDim.x + threadIdx.x;
    if (i < G4) g_bsum[i] = bih[i] + bhh[i];
    if (i == 0) g_ctr = 0u;
}

// ---------------- Generic GEMM:  C[M,N] = X[M,K] @ W[N,K]^T + bias[N], optional tanh ----------------
// Tiles: BM=128, BN=128, BK=16, 256 threads, 8x8 per-thread microtile, f32x2 FMA.
#define BM 128
#define BN 128
#define BK 16

template<bool TANH>
__global__ __launch_bounds__(256)
void gemm_bias(const float* __restrict__ X, const float* __restrict__ W,
               const float* __restrict__ bias, float* __restrict__ C,
               int lda, int ldc, int K)
{
    __shared__ float Xs[BK][BM + 1];   // [k][m], pad 129
    __shared__ float Ws[BK][BN + 2];   // [k][n], pad 130 (keeps rows 8B aligned)

    const int m0 = blockIdx.y * BM;
    const int n0 = blockIdx.x * BN;
    const int tid = threadIdx.x;

    const int lr = tid >> 1;          // 0..127 : row within tile
    const int lc = tid & 1;           // 0..1   : which 8-float chunk of the 16 K
    const float* Xp = X + (size_t)(m0 + lr) * lda + lc * 8;
    const float* Wp = W + (size_t)(n0 + lr) * K   + lc * 8;

    ull acc[8][4];
#pragma unroll
    for (int i = 0; i < 8; i++)
#pragma unroll
        for (int j = 0; j < 4; j++) acc[i][j] = 0ull;

    const int tm = tid >> 4;          // 0..15
    const int tn = tid & 15;          // 0..15

    const int ntiles = K / BK;
    for (int kt = 0; kt < ntiles; kt++) {
        float4 x0 = *(const float4*)(Xp);
        float4 x1 = *(const float4*)(Xp + 4);
        float4 w0 = *(const float4*)(Wp);
        float4 w1 = *(const float4*)(Wp + 4);
        Xp += BK; Wp += BK;

        __syncthreads();   // previous compute done before smem overwrite
        {
            const int kb = lc * 8;
            Xs[kb + 0][lr] = x0.x; Xs[kb + 1][lr] = x0.y;
            Xs[kb + 2][lr] = x0.z; Xs[kb + 3][lr] = x0.w;
            Xs[kb + 4][lr] = x1.x; Xs[kb + 5][lr] = x1.y;
            Xs[kb + 6][lr] = x1.z; Xs[kb + 7][lr] = x1.w;
            Ws[kb + 0][lr] = w0.x; Ws[kb + 1][lr] = w0.y;
            Ws[kb + 2][lr] = w0.z; Ws[kb + 3][lr] = w0.w;
            Ws[kb + 4][lr] = w1.x; Ws[kb + 5][lr] = w1.y;
            Ws[kb + 6][lr] = w1.z; Ws[kb + 7][lr] = w1.w;
        }
        __syncthreads();

#pragma unroll
        for (int kk = 0; kk < BK; kk++) {
            float a[8];
#pragma unroll
            for (int i = 0; i < 8; i++) a[i] = Xs[kk][tm * 8 + i];
            ull b2[4];
#pragma unroll
            for (int j = 0; j < 4; j++)
                b2[j] = *(const ull*)&Ws[kk][tn * 8 + 2 * j];
#pragma unroll
            for (int i = 0; i < 8; i++) {
                ull ai = pack2(a[i], a[i]);
#pragma unroll
                for (int j = 0; j < 4; j++)
                    acc[i][j] = ffma2(ai, b2[j], acc[i][j]);
            }
        }
    }

    // epilogue
#pragma unroll
    for (int i = 0; i < 8; i++) {
        const int m = m0 + tm * 8 + i;
        float* crow = C + (size_t)m * ldc + n0 + tn * 8;
#pragma unroll
        for (int j = 0; j < 4; j++) {
            float x, y;
            unpack2(acc[i][j], x, y);
            const int n = n0 + tn * 8 + 2 * j;
            x += bias[n];
            y += bias[n + 1];
            if (TANH) { x = tanhf(x); y = tanhf(y); }
            float2 v2 = make_float2(x, y);
            *(float2*)(crow + 2 * j) = v2;
        }
    }
}

// ---------------- Attention fusion: scores -> softmax -> weighted sum ----------------
// One warp per row. a,v,l cached in registers, reused for the output.
__global__ __launch_bounds__(256)
void fusion_kernel()
{
    const int warp = threadIdx.x >> 5;
    const int lane = threadIdx.x & 31;
    const int row  = blockIdx.x * 8 + warp;

    const float* crow = g_cat + (size_t)row * CAT_K;
    const float* xrow = g_ctx + (size_t)row * H_DIM;

    float av[16], vv[16], lv[16];
    float sa = 0.f, sv = 0.f, sl = 0.f;
#pragma unroll
    for (int q = 0; q < 16; q++) {
        const int k = lane + 32 * q;
        const float c = xrow[k];
        av[q] = crow[k];
        vv[q] = crow[512 + k];
        lv[q] = crow[1024 + k];
        sa = fmaf(av[q], c, sa);
        sv = fmaf(vv[q], c, sv);
        sl = fmaf(lv[q], c, sl);
    }
#pragma unroll
    for (int m = 16; m >= 1; m >>= 1) {
        sa += __shfl_xor_sync(0xffffffffu, sa, m);
        sv += __shfl_xor_sync(0xffffffffu, sv, m);
        sl += __shfl_xor_sync(0xffffffffu, sl, m);
    }
    const float mx = fmaxf(sa, fmaxf(sv, sl));
    const float ea = __expf(sa - mx);
    const float ev = __expf(sv - mx);
    const float el = __expf(sl - mx);
    const float inv = 1.0f / (ea + ev + el);
    const float wa = ea * inv, wv = ev * inv, wl = el * inv;

    float* frow = g_fus + (size_t)row * H_DIM;
#pragma unroll
    for (int q = 0; q < 16; q++) {
        const int k = lane + 32 * q;
        frow[k] = wa * av[q] + wv * vv[q] + wl * lv[q];
    }
}

// ---------------- Persistent LSTM ----------------
// 128 CTAs x 128 threads, all co-resident. CTA c owns h-columns [4c,4c+4).
// Warp g (0..3) computes gate g for those 4 columns x 16 batches.
// Whh slice lives in registers: lane holds, per row, 8 f32x2 at k = 2*lane + 64*i.
// h_{t-1} broadcast through double-buffered global + atomic-counter spin sync.
#define NCTA 128
#define OFF_R ((size_t)BB * SS * H_DIM)

__global__ __launch_bounds__(128)
void lstm_kernel(const float* __restrict__ h0, const float* __restrict__ c0,
                 const float* __restrict__ Whh, float* __restrict__ out)
{
    __shared__ __align__(16) float h_s[BB * H_DIM];   // 32KB
    __shared__ float gates_s[4][4][BB];

    const int tid  = threadIdx.x;
    const int g    = tid >> 5;          // warp id = gate index (i,f,g,o)
    const int lane = tid & 31;
    const int c    = blockIdx.x;        // 0..127

    // register-resident Whh slice: 4 rows (cols 4c..4c+3 of gate g)
    ull w2[4][8];
#pragma unroll
    for (int j = 0; j < 4; j++) {
        const float* wrow = Whh + (size_t)(g * H_DIM + 4 * c + j) * H_DIM;
#pragma unroll
        for (int i = 0; i < 8; i++)
            w2[j][i] = *(const ull*)(wrow + 2 * lane + 64 * i);
    }

    // combine-thread state (threads 0..63): (j_in, b) -> cell state in register
    const int jn = tid >> 4;   // 0..3 (valid for tid<64)
    const int b  = tid & 15;
    float c_val = 0.f;
    if (tid < 64) c_val = c0[b * H_DIM + 4 * c + jn];

    for (int t = 0; t < SS; t++) {
        // prefetch xg for this step (independent of the recurrence)
        float xv0 = 0.f, xv1 = 0.f, xv2 = 0.f, xv3 = 0.f;
        if (tid < 64) {
            const float* xr = g_xg + ((size_t)(b * SS + t)) * G4 + 4 * c + jn;
            xv0 = xr[0 * H_DIM];
            xv1 = xr[1 * H_DIM];
            xv2 = xr[2 * H_DIM];
            xv3 = xr[3 * H_DIM];
        }

        // wait for h_{t-1} to be globally visible
        if (t > 0) {
            if (tid == 0) {
                const unsigned target = (unsigned)NCTA * (unsigned)t;
                while (*(volatile unsigned*)&g_ctr < target) {}
                __threadfence();
            }
            __syncthreads();
        }

        // stage h_{t-1} into smem
        {
            const float* hsrc = (t == 0) ? h0 : (g_hbuf + (size_t)(t & 1) * (BB * H_DIM));
#pragma unroll
            for (int q = 0; q < 16; q++)
                ((float4*)h_s)[tid + 128 * q] = ((const float4*)hsrc)[tid + 128 * q];
        }
        __syncthreads();

        // gates partials:  Whh_rows . h_{t-1}
#pragma unroll 4
        for (int bb = 0; bb < BB; bb++) {
            ull hv[8];
#pragma unroll
            for (int i = 0; i < 8; i++)
                hv[i] = *(const ull*)&h_s[bb * H_DIM + 2 * lane + 64 * i];
            ull acc[4] = {0ull, 0ull, 0ull, 0ull};
#pragma unroll
            for (int i = 0; i < 8; i++)
#pragma unroll
                for (int j = 0; j < 4; j++)
                    acc[j] = ffma2(w2[j][i], hv[i], acc[j]);
#pragma unroll
            for (int j = 0; j < 4; j++) {
                float x, y;
                unpack2(acc[j], x, y);
                float s = x + y;
                s += __shfl_xor_sync(0xffffffffu, s, 16);
                s += __shfl_xor_sync(0xffffffffu, s, 8);
                s += __shfl_xor_sync(0xffffffffu, s, 4);
                s += __shfl_xor_sync(0xffffffffu, s, 2);
                s += __shfl_xor_sync(0xffffffffu, s, 1);
                if (lane == j) gates_s[g][j][bb] = s;
            }
        }
        __syncthreads();

        // gate combine + state update + write h
        if (tid < 64) {
            const float gi = gates_s[0][jn][b] + xv0;
            const float gf = gates_s[1][jn][b] + xv1;
            const float gg = gates_s[2][jn][b] + xv2;
            const float go = gates_s[3][jn][b] + xv3;
            const float iv = sigmf(gi);
            const float fv = sigmf(gf);
            const float gv = tanhf(gg);
            const float ov = sigmf(go);
            c_val = fv * c_val + iv * gv;
            const float h = ov * tanhf(c_val);
            const int col = 4 * c + jn;
            g_hbuf[(size_t)((t + 1) & 1) * (BB * H_DIM) + b * H_DIM + col] = h;
            out[((size_t)(b * SS + t)) * H_DIM + col] = h;
            if (t == SS - 1) {
                out[OFF_R + b * H_DIM + col]                 = h;      // hT
                out[OFF_R + BB * H_DIM + b * H_DIM + col]    = c_val;  // cT
            }
        }
        __threadfence();
        __syncthreads();
        if (tid == 0) atomicAdd(&g_ctr, 1u);
    }
}

// ---------------- Launch ----------------
extern "C" void kernel_launch(void* const* d_in, const int* in_sizes, int n_in,
                              void* d_out, int out_size)
{
    const float* a_in = (const float*)d_in[0];
    const float* v_in = (const float*)d_in[1];
    const float* l_in = (const float*)d_in[2];
    const float* h0   = (const float*)d_in[3];
    const float* c0   = (const float*)d_in[4];
    const float* Wa   = (const float*)d_in[5];
    const float* ba   = (const float*)d_in[6];
    const float* Wv   = (const float*)d_in[7];
    const float* bv   = (const float*)d_in[8];
    const float* Wl   = (const float*)d_in[9];
    const float* bl   = (const float*)d_in[10];
    const float* Wc   = (const float*)d_in[11];
    const float* bc   = (const float*)d_in[12];
    const float* Wih  = (const float*)d_in[13];
    const float* Whh  = (const float*)d_in[14];
    const float* bih  = (const float*)d_in[15];
    const float* bhh  = (const float*)d_in[16];
    float* out = (float*)d_out;

    float *cat, *ctx, *fus, *xg, *bsum;
    cudaGetSymbolAddress((void**)&cat,  g_cat);
    cudaGetSymbolAddress((void**)&ctx,  g_ctx);
    cudaGetSymbolAddress((void**)&fus,  g_fus);
    cudaGetSymbolAddress((void**)&xg,   g_xg);
    cudaGetSymbolAddress((void**)&bsum, g_bsum);

    init_kernel<<<2, 1024>>>(bih, bhh);

    // projections into the concat buffer (row stride 1536)
    gemm_bias<false><<<dim3(H_DIM / BN, ROWS / BM), 256>>>(a_in, Wa, ba, cat,          A_DIM, CAT_K, A_DIM);
    gemm_bias<false><<<dim3(H_DIM / BN, ROWS / BM), 256>>>(v_in, Wv, bv, cat + 512,    V_DIM, CAT_K, V_DIM);
    gemm_bias<false><<<dim3(H_DIM / BN, ROWS / BM), 256>>>(l_in, Wl, bl, cat + 1024,   L_DIM, CAT_K, L_DIM);

    // context = tanh(cat @ Wc^T + bc)
    gemm_bias<true><<<dim3(H_DIM / BN, ROWS / BM), 256>>>(cat, Wc, bc, ctx, CAT_K, H_DIM, CAT_K);

    // attention softmax fusion
    fusion_kernel<<<ROWS / 8, 256>>>();

    // xg = fusion @ Wih^T + (bih + bhh)
    gemm_bias<false><<<dim3(G4 / BN, ROWS / BM), 256>>>(fus, Wih, bsum, xg, H_DIM, G4, H_DIM);

    // recurrent LSTM (persistent, self-synchronizing)
    lstm_kernel<<<NCTA, 128>>>(h0, c0, Whh, out);
}

// round 3
// speedup vs baseline: 1.4307x; 1.4307x over previous
#include <cuda_runtime.h>
#include <cstdint>

typedef unsigned long long ull;

// ---------------- Problem constants ----------------
#define A_DIM 512
#define V_DIM 768
#define L_DIM 1024
#define H_DIM 512
#define BB    16
#define SS    2048
#define ROWS  (BB * SS)        // 32768
#define G4    (4 * H_DIM)      // 2048
#define CAT_K 1536

// ---------------- Scratch (device globals; no allocation allowed) ----------------
__device__ float g_cat[(size_t)ROWS * CAT_K];   // [rows,1536] : a|v|l concat
__device__ float g_ctx[(size_t)ROWS * H_DIM];   // context
__device__ float g_fus[(size_t)ROWS * H_DIM];   // fusion (LSTM input)
__device__ float g_xg [(size_t)ROWS * G4];      // fusion @ Wih^T + (bih+bhh)
__device__ float g_hbuf[2 * BB * H_DIM];        // double-buffered recurrent h
__device__ float g_bsum[G4];                    // bih + bhh
__device__ unsigned int g_ctr;                  // LSTM step sync counter

// ---------------- f32x2 packed helpers ----------------
__device__ __forceinline__ ull ffma2(ull a, ull b, ull c) {
    asm("fma.rn.f32x2 %0, %1, %2, %0;" : "+l"(c) : "l"(a), "l"(b));
    return c;
}
__device__ __forceinline__ ull pack2(float x, float y) {
    ull r; asm("mov.b64 %0, {%1, %2};" : "=l"(r) : "f"(x), "f"(y)); return r;
}
__device__ __forceinline__ void unpack2(ull v, float& x, float& y) {
    asm("mov.b64 {%0, %1}, %2;" : "=f"(x), "=f"(y) : "l"(v));
}
__device__ __forceinline__ float sigmf(float x) {
    return 1.0f / (1.0f + __expf(-x));
}

// ---------------- Init: reset counter + fold biases ----------------
__global__ void init_kernel(const float* __restrict__ bih,
                            const float* __restrict__ bhh) {
    int i = blockIdx.x * blockDim.x + threadIdx.x;
    if (i < G4) g_bsum[i] = bih[i] + bhh[i];
    if (i == 0) g_ctr = 0u;
}

// ---------------- GEMM:  C[M,N] = X[M,K] @ W[N,K]^T + bias[N], optional tanh ----------------
// BM=BN=128, BK=16, 256 threads, 8x8 microtile. Vectorized smem (LDS.128) +
// f32x2 FMA -> FMA-pipe bound.
#define BM 128
#define BN 128
#define BK 16

template<bool TANH>
__global__ __launch_bounds__(256, 2)
void gemm_bias(const float* __restrict__ X, const float* __restrict__ W,
               const float* __restrict__ bias, float* __restrict__ C,
               int lda, int ldc, int K)
{
    __shared__ __align__(16) float Xs[BK][BM + 4];   // rows 132 floats = 528B (16B aligned)
    __shared__ __align__(16) float Ws[BK][BN + 4];

    const int m0 = blockIdx.y * BM;
    const int n0 = blockIdx.x * BN;
    const int tid = threadIdx.x;

    const int lr = tid & 127;         // row within tile
    const int lc = tid >> 7;          // 0/1 : which 8-float K chunk
    const float* Xp = X + (size_t)(m0 + lr) * lda + lc * 8;
    const float* Wp = W + (size_t)(n0 + lr) * K   + lc * 8;

    ull acc[8][4];
#pragma unroll
    for (int i = 0; i < 8; i++)
#pragma unroll
        for (int j = 0; j < 4; j++) acc[i][j] = 0ull;

    const int tm = tid >> 4;          // 0..15
    const int tn = tid & 15;          // 0..15

    const int ntiles = K / BK;
    for (int kt = 0; kt < ntiles; kt++) {
        float4 x0 = *(const float4*)(Xp);
        float4 x1 = *(const float4*)(Xp + 4);
        float4 w0 = *(const float4*)(Wp);
        float4 w1 = *(const float4*)(Wp + 4);
        Xp += BK; Wp += BK;

        __syncthreads();   // previous compute done before smem overwrite
        {
            const int kb = lc * 8;
            Xs[kb + 0][lr] = x0.x; Xs[kb + 1][lr] = x0.y;
            Xs[kb + 2][lr] = x0.z; Xs[kb + 3][lr] = x0.w;
            Xs[kb + 4][lr] = x1.x; Xs[kb + 5][lr] = x1.y;
            Xs[kb + 6][lr] = x1.z; Xs[kb + 7][lr] = x1.w;
            Ws[kb + 0][lr] = w0.x; Ws[kb + 1][lr] = w0.y;
            Ws[kb + 2][lr] = w0.z; Ws[kb + 3][lr] = w0.w;
            Ws[kb + 4][lr] = w1.x; Ws[kb + 5][lr] = w1.y;
            Ws[kb + 6][lr] = w1.z; Ws[kb + 7][lr] = w1.w;
        }
        __syncthreads();

#pragma unroll
        for (int kk = 0; kk < BK; kk++) {
            // X fragment: 2x LDS.128 (broadcast within half-warps)
            float4 a0 = *(const float4*)&Xs[kk][tm * 8];
            float4 a1 = *(const float4*)&Xs[kk][tm * 8 + 4];
            // W fragment: 2x LDS.128 read directly as f32x2 pairs
            ulonglong2 b0 = *(const ulonglong2*)&Ws[kk][tn * 8];
            ulonglong2 b1 = *(const ulonglong2*)&Ws[kk][tn * 8 + 4];
            ull b2[4] = { b0.x, b0.y, b1.x, b1.y };
            float a[8] = { a0.x, a0.y, a0.z, a0.w, a1.x, a1.y, a1.z, a1.w };
#pragma unroll
            for (int i = 0; i < 8; i++) {
                ull ai = pack2(a[i], a[i]);
#pragma unroll
                for (int j = 0; j < 4; j++)
                    acc[i][j] = ffma2(ai, b2[j], acc[i][j]);
            }
        }
    }

    // epilogue
#pragma unroll
    for (int i = 0; i < 8; i++) {
        const int m = m0 + tm * 8 + i;
        float* crow = C + (size_t)m * ldc + n0 + tn * 8;
#pragma unroll
        for (int j = 0; j < 4; j++) {
            float x, y;
            unpack2(acc[i][j], x, y);
            const int n = n0 + tn * 8 + 2 * j;
            x += bias[n];
            y += bias[n + 1];
            if (TANH) { x = tanhf(x); y = tanhf(y); }
            float2 v2 = make_float2(x, y);
            *(float2*)(crow + 2 * j) = v2;
        }
    }
}

// ---------------- Attention fusion: scores -> softmax -> weighted sum ----------------
__global__ __launch_bounds__(256)
void fusion_kernel()
{
    const int warp = threadIdx.x >> 5;
    const int lane = threadIdx.x & 31;
    const int row  = blockIdx.x * 8 + warp;

    const float* crow = g_cat + (size_t)row * CAT_K;
    const float* xrow = g_ctx + (size_t)row * H_DIM;

    float av[16], vv[16], lv[16];
    float sa = 0.f, sv = 0.f, sl = 0.f;
#pragma unroll
    for (int q = 0; q < 16; q++) {
        const int k = lane + 32 * q;
        const float c = xrow[k];
        av[q] = crow[k];
        vv[q] = crow[512 + k];
        lv[q] = crow[1024 + k];
        sa = fmaf(av[q], c, sa);
        sv = fmaf(vv[q], c, sv);
        sl = fmaf(lv[q], c, sl);
    }
#pragma unroll
    for (int m = 16; m >= 1; m >>= 1) {
        sa += __shfl_xor_sync(0xffffffffu, sa, m);
        sv += __shfl_xor_sync(0xffffffffu, sv, m);
        sl += __shfl_xor_sync(0xffffffffu, sl, m);
    }
    const float mx = fmaxf(sa, fmaxf(sv, sl));
    const float ea = __expf(sa - mx);
    const float ev = __expf(sv - mx);
    const float el = __expf(sl - mx);
    const float inv = 1.0f / (ea + ev + el);
    const float wa = ea * inv, wv = ev * inv, wl = el * inv;

    float* frow = g_fus + (size_t)row * H_DIM;
#pragma unroll
    for (int q = 0; q < 16; q++) {
        const int k = lane + 32 * q;
        frow[k] = wa * av[q] + wv * vv[q] + wl * lv[q];
    }
}

// ---------------- Persistent LSTM ----------------
// 128 CTAs x 256 threads, all co-resident. CTA c owns h-columns [4c,4c+4).
// Warp layout: gpair = warp>>2 (gates {0,1} or {2,3}), bq = warp&3 (4 batches).
// Each thread holds 8 W-rows x 16 K-floats register-resident; h read via LDS.128.
#define NCTA 128
#define OFF_R ((size_t)BB * SS * H_DIM)

__global__ __launch_bounds__(256, 1)
void lstm_kernel(const float* __restrict__ h0, const float* __restrict__ c0,
                 const float* __restrict__ Whh, float* __restrict__ out)
{
    __shared__ __align__(16) float h_s[BB * H_DIM];   // 32KB
    __shared__ float gates_s[4][4][BB];

    const int tid   = threadIdx.x;
    const int w     = tid >> 5;
    const int lane  = tid & 31;
    const int c     = blockIdx.x;        // 0..127
    const int gpair = w >> 2;            // 0: gates 0,1   1: gates 2,3
    const int bq    = w & 3;             // batch quarter

    // register-resident Whh rows: r -> gate = 2*gpair + (r>>2), j = r&3
    // lane K-slice: k = 4*lane + 128*ic + {0..3}, ic = 0..3  (16 floats)
    ull wgt[8][8];
#pragma unroll
    for (int r = 0; r < 8; r++) {
        const int gate = 2 * gpair + (r >> 2);
        const int j    = r & 3;
        const float* wr = Whh + (size_t)(gate * H_DIM + 4 * c + j) * H_DIM;
#pragma unroll
        for (int ic = 0; ic < 4; ic++) {
            ulonglong2 u = *(const ulonglong2*)(wr + 4 * lane + 128 * ic);
            wgt[r][2 * ic]     = u.x;
            wgt[r][2 * ic + 1] = u.y;
        }
    }

    // combine-thread state (threads 0..63): (jn, b)
    const int jn = tid >> 4;   // 0..3
    const int b  = tid & 15;
    float c_val = 0.f;
    if (tid < 64) c_val = c0[b * H_DIM + 4 * c + jn];

    for (int t = 0; t < SS; t++) {
        // prefetch xg for this step (independent of the recurrence)
        float xv0 = 0.f, xv1 = 0.f, xv2 = 0.f, xv3 = 0.f;
        if (tid < 64) {
            const float* xr = g_xg + ((size_t)(b * SS + t)) * G4 + 4 * c + jn;
            xv0 = xr[0 * H_DIM];
            xv1 = xr[1 * H_DIM];
            xv2 = xr[2 * H_DIM];
            xv3 = xr[3 * H_DIM];
        }

        // wait for h_{t-1} to be globally visible
        if (t > 0) {
            if (tid == 0) {
                const unsigned target = (unsigned)NCTA * (unsigned)t;
                while (*(volatile unsigned*)&g_ctr < target) {}
                __threadfence();
            }
            __syncthreads();
        }

        // stage h_{t-1} into smem (8192 floats, 8 float4 per thread)
        {
            const float* hsrc = (t == 0) ? h0 : (g_hbuf + (size_t)(t & 1) * (BB * H_DIM));
#pragma unroll
            for (int q = 0; q < 8; q++)
                ((float4*)h_s)[tid + 256 * q] = ((const float4*)hsrc)[tid + 256 * q];
        }
        __syncthreads();

        // gate partials:  (8 rows) . h[bb]  for 4 batches
#pragma unroll
        for (int bi = 0; bi < 4; bi++) {
            const int bb = 4 * bq + bi;
            ull hv[8];
#pragma unroll
            for (int ic = 0; ic < 4; ic++) {
                ulonglong2 u = *(const ulonglong2*)&h_s[bb * H_DIM + 4 * lane + 128 * ic];
                hv[2 * ic]     = u.x;
                hv[2 * ic + 1] = u.y;
            }
            ull acc[8];
#pragma unroll
            for (int r = 0; r < 8; r++) acc[r] = 0ull;
#pragma unroll
            for (int kq = 0; kq < 8; kq++)
#pragma unroll
                for (int r = 0; r < 8; r++)
                    acc[r] = ffma2(wgt[r][kq], hv[kq], acc[r]);
#pragma unroll
            for (int r = 0; r < 8; r++) {
                float x, y;
                unpack2(acc[r], x, y);
                float s = x + y;
                s += __shfl_xor_sync(0xffffffffu, s, 16);
                s += __shfl_xor_sync(0xffffffffu, s, 8);
                s += __shfl_xor_sync(0xffffffffu, s, 4);
                s += __shfl_xor_sync(0xffffffffu, s, 2);
                s += __shfl_xor_sync(0xffffffffu, s, 1);
                if (lane == r) gates_s[2 * gpair + (r >> 2)][r & 3][bb] = s;
            }
        }
        __syncthreads();

        // gate combine + state update + write h
        if (tid < 64) {
            const float gi = gates_s[0][jn][b] + xv0;
            const float gf = gates_s[1][jn][b] + xv1;
            const float gg = gates_s[2][jn][b] + xv2;
            const float go = gates_s[3][jn][b] + xv3;
            const float iv = sigmf(gi);
            const float fv = sigmf(gf);
            const float gv = tanhf(gg);
            const float ov = sigmf(go);
            c_val = fv * c_val + iv * gv;
            const float h = ov * tanhf(c_val);
            const int col = 4 * c + jn;
            g_hbuf[(size_t)((t + 1) & 1) * (BB * H_DIM) + b * H_DIM + col] = h;
            out[((size_t)(b * SS + t)) * H_DIM + col] = h;
            if (t == SS - 1) {
                out[OFF_R + b * H_DIM + col]              = h;      // hT
                out[OFF_R + BB * H_DIM + b * H_DIM + col] = c_val;  // cT
            }
        }
        __threadfence();
        __syncthreads();
        if (tid == 0) atomicAdd(&g_ctr, 1u);
    }
}

// ---------------- Launch ----------------
extern "C" void kernel_launch(void* const* d_in, const int* in_sizes, int n_in,
                              void* d_out, int out_size)
{
    const float* a_in = (const float*)d_in[0];
    const float* v_in = (const float*)d_in[1];
    const float* l_in = (const float*)d_in[2];
    const float* h0   = (const float*)d_in[3];
    const float* c0   = (const float*)d_in[4];
    const float* Wa   = (const float*)d_in[5];
    const float* ba   = (const float*)d_in[6];
    const float* Wv   = (const float*)d_in[7];
    const float* bv   = (const float*)d_in[8];
    const float* Wl   = (const float*)d_in[9];
    const float* bl   = (const float*)d_in[10];
    const float* Wc   = (const float*)d_in[11];
    const float* bc   = (const float*)d_in[12];
    const float* Wih  = (const float*)d_in[13];
    const float* Whh  = (const float*)d_in[14];
    const float* bih  = (const float*)d_in[15];
    const float* bhh  = (const float*)d_in[16];
    float* out = (float*)d_out;

    float *cat, *ctx, *fus, *xg, *bsum;
    cudaGetSymbolAddress((void**)&cat,  g_cat);
    cudaGetSymbolAddress((void**)&ctx,  g_ctx);
    cudaGetSymbolAddress((void**)&fus,  g_fus);
    cudaGetSymbolAddress((void**)&xg,   g_xg);
    cudaGetSymbolAddress((void**)&bsum, g_bsum);

    init_kernel<<<2, 1024>>>(bih, bhh);

    // projections into the concat buffer (row stride 1536)
    gemm_bias<false><<<dim3(H_DIM / BN, ROWS / BM), 256>>>(a_in, Wa, ba, cat,        A_DIM, CAT_K, A_DIM);
    gemm_bias<false><<<dim3(H_DIM / BN, ROWS / BM), 256>>>(v_in, Wv, bv, cat + 512,  V_DIM, CAT_K, V_DIM);
    gemm_bias<false><<<dim3(H_DIM / BN, ROWS / BM), 256>>>(l_in, Wl, bl, cat + 1024, L_DIM, CAT_K, L_DIM);

    // context = tanh(cat @ Wc^T + bc)
    gemm_bias<true><<<dim3(H_DIM / BN, ROWS / BM), 256>>>(cat, Wc, bc, ctx, CAT_K, H_DIM, CAT_K);

    // attention softmax fusion
    fusion_kernel<<<ROWS / 8, 256>>>();

    // xg = fusion @ Wih^T + (bih + bhh)
    gemm_bias<false><<<dim3(G4 / BN, ROWS / BM), 256>>>(fus, Wih, bsum, xg, H_DIM, G4, H_DIM);

    // recurrent LSTM (persistent, self-synchronizing)
    lstm_kernel<<<NCTA, 256>>>(h0, c0, Whh, out);
}

// round 7
// speedup vs baseline: 1.8058x; 1.2622x over previous
#include <cuda_runtime.h>
#include <cuda_bf16.h>
#include <cstdint>

typedef unsigned long long ull;
typedef unsigned short u16;
typedef unsigned int u32;

// ---------------- Problem constants ----------------
#define A_DIM 512
#define V_DIM 768
#define L_DIM 1024
#define H_DIM 512
#define BB    16
#define SS    2048
#define ROWS  (BB * SS)        // 32768
#define G4    (4 * H_DIM)      // 2048
#define CAT_K 1536

// ---------------- Scratch (device globals; no allocation allowed) ----------------
__device__ float g_cat[(size_t)ROWS * CAT_K];   // fp32 a|v|l concat (for fusion)
__device__ float g_ctx[(size_t)ROWS * H_DIM];   // context fp32
__device__ float g_xg [(size_t)ROWS * G4];      // LSTM input gates fp32
__device__ float g_hbuf[2 * BB * H_DIM];
__device__ float g_bsum[G4];
__device__ unsigned int g_ctr;

// bf16 hi/lo split operand buffers (u16), 16B aligned for uint4 loads
__device__ __align__(16) u16 g_ahi[(size_t)ROWS * A_DIM],  g_alo[(size_t)ROWS * A_DIM];
__device__ __align__(16) u16 g_vhi[(size_t)ROWS * V_DIM],  g_vlo[(size_t)ROWS * V_DIM];
__device__ __align__(16) u16 g_lhi[(size_t)ROWS * L_DIM],  g_llo[(size_t)ROWS * L_DIM];
__device__ __align__(16) u16 g_cathi[(size_t)ROWS * CAT_K], g_catlo[(size_t)ROWS * CAT_K];
__device__ __align__(16) u16 g_fushi[(size_t)ROWS * H_DIM], g_fuslo[(size_t)ROWS * H_DIM];
__device__ __align__(16) u16 g_wahi[H_DIM * A_DIM],  g_walo[H_DIM * A_DIM];
__device__ __align__(16) u16 g_wvhi[H_DIM * V_DIM],  g_wvlo[H_DIM * V_DIM];
__device__ __align__(16) u16 g_wlhi[H_DIM * L_DIM],  g_wllo[H_DIM * L_DIM];
__device__ __align__(16) u16 g_wchi[H_DIM * CAT_K],  g_wclo[H_DIM * CAT_K];
__device__ __align__(16) u16 g_wihhi[G4 * H_DIM],    g_wihlo[G4 * H_DIM];

// ---------------- helpers ----------------
__device__ __forceinline__ ull ffma2(ull a, ull b, ull c) {
    asm("fma.rn.f32x2 %0, %1, %2, %0;" : "+l"(c) : "l"(a), "l"(b));
    return c;
}
__device__ __forceinline__ void unpack2(ull v, float& x, float& y) {
    asm("mov.b64 {%0, %1}, %2;" : "=f"(x), "=f"(y) : "l"(v));
}
__device__ __forceinline__ float sigmf(float x) { return 1.0f / (1.0f + __expf(-x)); }

__device__ __forceinline__ u32 smem_u32(const void* p) {
    u32 a;
    asm("{ .reg .u64 t; cvta.to.shared.u64 t, %1; cvt.u32.u64 %0, t; }" : "=r"(a) : "l"(p));
    return a;
}

#define SWZ128(x) ((x) ^ (((x) >> 3) & 0x70))

__device__ __forceinline__ void ldsm4(u32& r0, u32& r1, u32& r2, u32& r3, u32 addr) {
    asm volatile("ldmatrix.sync.aligned.m8n8.x4.shared.b16 {%0,%1,%2,%3}, [%4];"
        : "=r"(r0), "=r"(r1), "=r"(r2), "=r"(r3) : "r"(addr));
}
__device__ __forceinline__ void mma16816(float* c, u32 a0, u32 a1, u32 a2, u32 a3,
                                         u32 b0, u32 b1) {
    asm volatile("mma.sync.aligned.m16n8k16.row.col.f32.bf16.bf16.f32 "
        "{%0,%1,%2,%3}, {%4,%5,%6,%7}, {%8,%9}, {%0,%1,%2,%3};"
        : "+f"(c[0]), "+f"(c[1]), "+f"(c[2]), "+f"(c[3])
        : "r"(a0), "r"(a1), "r"(a2), "r"(a3), "r"(b0), "r"(b1));
}

// ---------------- Init ----------------
__global__ void init_kernel(const float* __restrict__ bih, const float* __restrict__ bhh) {
    int i = blockIdx.x * blockDim.x + threadIdx.x;
    if (i < G4) g_bsum[i] = bih[i] + bhh[i];
    if (i == 0) g_ctr = 0u;
}

// ---------------- fp32 -> bf16 hi/lo split ----------------
__global__ void split_kernel(const float* __restrict__ s, u16* __restrict__ hi,
                             u16* __restrict__ lo, int n) {
    int i = blockIdx.x * blockDim.x + threadIdx.x;
    if (i < n) {
        float x = s[i];
        __nv_bfloat16 h = __float2bfloat16(x);
        float r = x - __bfloat162float(h);
        __nv_bfloat16 l = __float2bfloat16(r);
        hi[i] = *(u16*)&h;
        lo[i] = *(u16*)&l;
    }
}

// ---------------- mma.sync GEMM:  C[M,N] = X[M,K] @ W[N,K]^T + bias ----------------
// bf16 split, 3 passes (Xhi*Whi + Xhi*Wlo + Xlo*Whi) accumulated in fp32 regs.
// BM=BN=128, BK=64 (128B SW128 rows). 256 threads = 8 warps (4m x 2n), warp 32x64.
// MODE 0: fp32 out + bf16 hi/lo out.  MODE 1: tanh fp32 out.  MODE 2: fp32 out.
template<int MODE>
__global__ __launch_bounds__(256, 2)
void mma_gemm(const u16* __restrict__ Xhi, const u16* __restrict__ Xlo,
              const u16* __restrict__ Whi, const u16* __restrict__ Wlo,
              const float* __restrict__ bias, float* __restrict__ Cf,
              u16* __restrict__ Chi, u16* __restrict__ Clo,
              int K, int ldc)
{
    __shared__ __align__(16) u16 Asm[128 * 64];   // 16KB
    __shared__ __align__(16) u16 Bsm[128 * 64];   // 16KB

    const int tid  = threadIdx.x;
    const int lane = tid & 31;
    const int w    = tid >> 5;
    const int wm   = w & 3;         // m quarter (32 rows)
    const int wn   = w >> 2;        // n half (64 cols)
    const int m0 = blockIdx.y * 128;
    const int n0 = blockIdx.x * 128;

    float acc[2][8][4];
#pragma unroll
    for (int i = 0; i < 2; i++)
#pragma unroll
        for (int j = 0; j < 8; j++)
#pragma unroll
            for (int q = 0; q < 4; q++) acc[i][j][q] = 0.f;

    const u32 sA = smem_u32(Asm);
    const u32 sB = smem_u32(Bsm);

    // ldmatrix per-lane source rows (within tile) and K-byte offsets.
    // A (x4, non-trans): lanes 0-7 -> m0-7@k0, 8-15 -> m8-15@k0,
    //                    16-23 -> m0-7@k+8, 24-31 -> m8-15@k+8
    const int a_row = wm * 32 + (lane & 15);                       // + mt*16
    const int a_kb  = (lane >> 4) * 16;
    // B (x4, non-trans): lanes 0-7 -> n0-7@k0, 8-15 -> n0-7@k+8,
    //                    16-23 -> n8-15@k0, 24-31 -> n8-15@k+8
    const int b_row = wn * 64 + (lane & 7) + ((lane >> 4) << 3);   // + nt*16
    const int b_kb  = ((lane >> 3) & 1) * 16;

    const u16* Xs[3] = { Xhi, Xhi, Xlo };
    const u16* Ws[3] = { Whi, Wlo, Whi };
    const int KP = K / 64;
    const int NC = 3 * KP;

    // loader indexing: 1024 16B-chunks per tile, 4 per thread
    for (int ch = 0; ch < NC; ch++) {
        const int pass = ch / KP, kk = ch % KP;
        const u16* Ap = Xs[pass] + (size_t)m0 * K + kk * 64;
        const u16* Bp = Ws[pass] + (size_t)n0 * K + kk * 64;

        uint4 ar[4], br[4];
#pragma unroll
        for (int i = 0; i < 4; i++) {
            const int id  = tid + 256 * i;
            const int row = id >> 3;
            const int c   = id & 7;
            ar[i] = *(const uint4*)(Ap + (size_t)row * K + c * 8);
            br[i] = *(const uint4*)(Bp + (size_t)row * K + c * 8);
        }

        __syncthreads();   // previous compute done before smem overwrite
#pragma unroll
        for (int i = 0; i < 4; i++) {
            const int id  = tid + 256 * i;
            const int row = id >> 3;
            const int c   = id & 7;
            const int off = SWZ128(row * 128 + c * 16);
            *(uint4*)((char*)Asm + off) = ar[i];
            *(uint4*)((char*)Bsm + off) = br[i];
        }
        __syncthreads();

#pragma unroll
        for (int ks = 0; ks < 4; ks++) {
            const int kb = ks * 32;   // 16 k-elements = 32 bytes
            u32 a[2][4];
#pragma unroll
            for (int mt = 0; mt < 2; mt++) {
                const u32 addr = sA + SWZ128((a_row + mt * 16) * 128 + a_kb + kb);
                ldsm4(a[mt][0], a[mt][1], a[mt][2], a[mt][3], addr);
            }
#pragma unroll
            for (int nt = 0; nt < 4; nt++) {
                u32 b0, b1, b2, b3;
                const u32 addr = sB + SWZ128((b_row + nt * 16) * 128 + b_kb + kb);
                ldsm4(b0, b1, b2, b3, addr);
#pragma unroll
                for (int mt = 0; mt < 2; mt++) {
                    mma16816(acc[mt][2 * nt],     a[mt][0], a[mt][1], a[mt][2], a[mt][3], b0, b1);
                    mma16816(acc[mt][2 * nt + 1], a[mt][0], a[mt][1], a[mt][2], a[mt][3], b2, b3);
                }
            }
        }
    }

    // epilogue: per-fragment writes
    const int mb = m0 + wm * 32 + (lane >> 2);
    const int nb = n0 + wn * 64 + (lane & 3) * 2;
#pragma unroll
    for (int mt = 0; mt < 2; mt++) {
#pragma unroll
        for (int nt = 0; nt < 8; nt++) {
            const int n = nb + nt * 8;
            const float b0 = bias[n], b1 = bias[n + 1];
#pragma unroll
            for (int h = 0; h < 2; h++) {
                const int m = mb + mt * 16 + h * 8;
                float v0 = acc[mt][nt][2 * h]     + b0;
                float v1 = acc[mt][nt][2 * h + 1] + b1;
                if (MODE == 1) { v0 = tanhf(v0); v1 = tanhf(v1); }
                *(float2*)&Cf[(size_t)m * ldc + n] = make_float2(v0, v1);
                if (MODE == 0) {
                    __nv_bfloat16 h0 = __float2bfloat16(v0);
                    __nv_bfloat16 h1 = __float2bfloat16(v1);
                    float r0 = v0 - __bfloat162float(h0);
                    float r1 = v1 - __bfloat162float(h1);
                    __nv_bfloat16 l0 = __float2bfloat16(r0);
                    __nv_bfloat16 l1 = __float2bfloat16(r1);
                    u32 hp = (u32)*(u16*)&h0 | ((u32)*(u16*)&h1 << 16);
                    u32 lp = (u32)*(u16*)&l0 | ((u32)*(u16*)&l1 << 16);
                    *(u32*)&Chi[(size_t)m * ldc + n] = hp;
                    *(u32*)&Clo[(size_t)m * ldc + n] = lp;
                }
            }
        }
    }
}

// ---------------- Attention fusion -> bf16 hi/lo fusion ----------------
__global__ __launch_bounds__(256)
void fusion_kernel()
{
    const int warp = threadIdx.x >> 5;
    const int lane = threadIdx.x & 31;
    const int row  = blockIdx.x * 8 + warp;

    const float* crow = g_cat + (size_t)row * CAT_K;
    const float* xrow = g_ctx + (size_t)row * H_DIM;

    float av[16], vv[16], lv[16];
    float sa = 0.f, sv = 0.f, sl = 0.f;
#pragma unroll
    for (int q = 0; q < 16; q++) {
        const int k = lane + 32 * q;
        const float c = xrow[k];
        av[q] = crow[k];
        vv[q] = crow[512 + k];
        lv[q] = crow[1024 + k];
        sa = fmaf(av[q], c, sa);
        sv = fmaf(vv[q], c, sv);
        sl = fmaf(lv[q], c, sl);
    }
#pragma unroll
    for (int m = 16; m >= 1; m >>= 1) {
        sa += __shfl_xor_sync(0xffffffffu, sa, m);
        sv += __shfl_xor_sync(0xffffffffu, sv, m);
        sl += __shfl_xor_sync(0xffffffffu, sl, m);
    }
    const float mx = fmaxf(sa, fmaxf(sv, sl));
    const float ea = __expf(sa - mx);
    const float ev = __expf(sv - mx);
    const float el = __expf(sl - mx);
    const float inv = 1.0f / (ea + ev + el);
    const float wa = ea * inv, wv = ev * inv, wl = el * inv;

    u16* fh = g_fushi + (size_t)row * H_DIM;
    u16* fl = g_fuslo + (size_t)row * H_DIM;
#pragma unroll
    for (int q = 0; q < 16; q++) {
        const int k = lane + 32 * q;
        const float v = wa * av[q] + wv * vv[q] + wl * lv[q];
        __nv_bfloat16 h = __float2bfloat16(v);
        float rr = v - __bfloat162float(h);
        __nv_bfloat16 l = __float2bfloat16(rr);
        fh[k] = *(u16*)&h;
        fl[k] = *(u16*)&l;
    }
}

// ---------------- Persistent LSTM (unchanged) ----------------
#define NCTA 128
#define OFF_R ((size_t)BB * SS * H_DIM)

__global__ __launch_bounds__(256, 1)
void lstm_kernel(const float* __restrict__ h0, const float* __restrict__ c0,
                 const float* __restrict__ Whh, float* __restrict__ out)
{
    __shared__ __align__(16) float h_s[BB * H_DIM];
    __shared__ float gates_s[4][4][BB];

    const int tid   = threadIdx.x;
    const int w     = tid >> 5;
    const int lane  = tid & 31;
    const int c     = blockIdx.x;
    const int gpair = w >> 2;
    const int bq    = w & 3;

    ull wgt[8][8];
#pragma unroll
    for (int r = 0; r < 8; r++) {
        const int gate = 2 * gpair + (r >> 2);
        const int j    = r & 3;
        const float* wr = Whh + (size_t)(gate * H_DIM + 4 * c + j) * H_DIM;
#pragma unroll
        for (int ic = 0; ic < 4; ic++) {
            ulonglong2 u = *(const ulonglong2*)(wr + 4 * lane + 128 * ic);
            wgt[r][2 * ic]     = u.x;
            wgt[r][2 * ic + 1] = u.y;
        }
    }

    const int jn = tid >> 4;
    const int b  = tid & 15;
    float c_val = 0.f;
    if (tid < 64) c_val = c0[b * H_DIM + 4 * c + jn];

    for (int t = 0; t < SS; t++) {
        float xv0 = 0.f, xv1 = 0.f, xv2 = 0.f, xv3 = 0.f;
        if (tid < 64) {
            const float* xr = g_xg + ((size_t)(b * SS + t)) * G4 + 4 * c + jn;
            xv0 = xr[0 * H_DIM];
            xv1 = xr[1 * H_DIM];
            xv2 = xr[2 * H_DIM];
            xv3 = xr[3 * H_DIM];
        }

        if (t > 0) {
            if (tid == 0) {
                const unsigned target = (unsigned)NCTA * (unsigned)t;
                while (*(volatile unsigned*)&g_ctr < target) {}
                __threadfence();
            }
            __syncthreads();
        }

        {
            const float* hsrc = (t == 0) ? h0 : (g_hbuf + (size_t)(t & 1) * (BB * H_DIM));
#pragma unroll
            for (int q = 0; q < 8; q++)
                ((float4*)h_s)[tid + 256 * q] = ((const float4*)hsrc)[tid + 256 * q];
        }
        __syncthreads();

#pragma unroll
        for (int bi = 0; bi < 4; bi++) {
            const int bb = 4 * bq + bi;
            ull hv[8];
#pragma unroll
            for (int ic = 0; ic < 4; ic++) {
                ulonglong2 u = *(const ulonglong2*)&h_s[bb * H_DIM + 4 * lane + 128 * ic];
                hv[2 * ic]     = u.x;
                hv[2 * ic + 1] = u.y;
            }
            ull acc[8];
#pragma unroll
            for (int r = 0; r < 8; r++) acc[r] = 0ull;
#pragma unroll
            for (int kq = 0; kq < 8; kq++)
#pragma unroll
                for (int r = 0; r < 8; r++)
                    acc[r] = ffma2(wgt[r][kq], hv[kq], acc[r]);
#pragma unroll
            for (int r = 0; r < 8; r++) {
                float x, y;
                unpack2(acc[r], x, y);
                float s = x + y;
                s += __shfl_xor_sync(0xffffffffu, s, 16);
                s += __shfl_xor_sync(0xffffffffu, s, 8);
                s += __shfl_xor_sync(0xffffffffu, s, 4);
                s += __shfl_xor_sync(0xffffffffu, s, 2);
                s += __shfl_xor_sync(0xffffffffu, s, 1);
                if (lane == r) gates_s[2 * gpair + (r >> 2)][r & 3][bb] = s;
            }
        }
        __syncthreads();

        if (tid < 64) {
            const float gi = gates_s[0][jn][b] + xv0;
            const float gf = gates_s[1][jn][b] + xv1;
            const float gg = gates_s[2][jn][b] + xv2;
            const float go = gates_s[3][jn][b] + xv3;
            const float iv = sigmf(gi);
            const float fv = sigmf(gf);
            const float gv = tanhf(gg);
            const float ov = sigmf(go);
            c_val = fv * c_val + iv * gv;
            const float h = ov * tanhf(c_val);
            const int col = 4 * c + jn;
            g_hbuf[(size_t)((t + 1) & 1) * (BB * H_DIM) + b * H_DIM + col] = h;
            out[((size_t)(b * SS + t)) * H_DIM + col] = h;
            if (t == SS - 1) {
                out[OFF_R + b * H_DIM + col]              = h;
                out[OFF_R + BB * H_DIM + b * H_DIM + col] = c_val;
            }
        }
        __threadfence();
        __syncthreads();
        if (tid == 0) atomicAdd(&g_ctr, 1u);
    }
}

// ---------------- Launch ----------------
extern "C" void kernel_launch(void* const* d_in, const int* in_sizes, int n_in,
                              void* d_out, int out_size)
{
    const float* a_in = (const float*)d_in[0];
    const float* v_in = (const float*)d_in[1];
    const float* l_in = (const float*)d_in[2];
    const float* h0   = (const float*)d_in[3];
    const float* c0   = (const float*)d_in[4];
    const float* Wa   = (const float*)d_in[5];
    const float* ba   = (const float*)d_in[6];
    const float* Wv   = (const float*)d_in[7];
    const float* bv   = (const float*)d_in[8];
    const float* Wl   = (const float*)d_in[9];
    const float* bl   = (const float*)d_in[10];
    const float* Wc   = (const float*)d_in[11];
    const float* bc   = (const float*)d_in[12];
    const float* Wih  = (const float*)d_in[13];
    const float* Whh  = (const float*)d_in[14];
    const float* bih  = (const float*)d_in[15];
    const float* bhh  = (const float*)d_in[16];
    float* out = (float*)d_out;

    float *cat, *ctx, *xg, *bsum;
    cudaGetSymbolAddress((void**)&cat,  g_cat);
    cudaGetSymbolAddress((void**)&ctx,  g_ctx);
    cudaGetSymbolAddress((void**)&xg,   g_xg);
    cudaGetSymbolAddress((void**)&bsum, g_bsum);
    u16 *ahi,*alo,*vhi,*vlo,*lhi,*llo,*cathi,*catlo,*fushi,*fuslo;
    u16 *wahi,*walo,*wvhi,*wvlo,*wlhi,*wllo,*wchi,*wclo,*wihhi,*wihlo;
    cudaGetSymbolAddress((void**)&ahi, g_ahi);   cudaGetSymbolAddress((void**)&alo, g_alo);
    cudaGetSymbolAddress((void**)&vhi, g_vhi);   cudaGetSymbolAddress((void**)&vlo, g_vlo);
    cudaGetSymbolAddress((void**)&lhi, g_lhi);   cudaGetSymbolAddress((void**)&llo, g_llo);
    cudaGetSymbolAddress((void**)&cathi, g_cathi); cudaGetSymbolAddress((void**)&catlo, g_catlo);
    cudaGetSymbolAddress((void**)&fushi, g_fushi); cudaGetSymbolAddress((void**)&fuslo, g_fuslo);
    cudaGetSymbolAddress((void**)&wahi, g_wahi); cudaGetSymbolAddress((void**)&walo, g_walo);
    cudaGetSymbolAddress((void**)&wvhi, g_wvhi); cudaGetSymbolAddress((void**)&wvlo, g_wvlo);
    cudaGetSymbolAddress((void**)&wlhi, g_wlhi); cudaGetSymbolAddress((void**)&wllo, g_wllo);
    cudaGetSymbolAddress((void**)&wchi, g_wchi); cudaGetSymbolAddress((void**)&wclo, g_wclo);
    cudaGetSymbolAddress((void**)&wihhi, g_wihhi); cudaGetSymbolAddress((void**)&wihlo, g_wihlo);

    init_kernel<<<2, 1024>>>(bih, bhh);

    auto SPLIT = [&](const float* s, u16* h, u16* l, int n) {
        split_kernel<<<(n + 255) / 256, 256>>>(s, h, l, n);
    };
    SPLIT(a_in, ahi, alo, ROWS * A_DIM);
    SPLIT(v_in, vhi, vlo, ROWS * V_DIM);
    SPLIT(l_in, lhi, llo, ROWS * L_DIM);
    SPLIT(Wa, wahi, walo, H_DIM * A_DIM);
    SPLIT(Wv, wvhi, wvlo, H_DIM * V_DIM);
    SPLIT(Wl, wlhi, wllo, H_DIM * L_DIM);
    SPLIT(Wc, wchi, wclo, H_DIM * CAT_K);
    SPLIT(Wih, wihhi, wihlo, G4 * H_DIM);

    // projections -> cat fp32 + cat hi/lo (row stride 1536)
    mma_gemm<0><<<dim3(4, 256), 256>>>(ahi, alo, wahi, walo, ba,
        cat,        cathi,        catlo,        A_DIM, CAT_K);
    mma_gemm<0><<<dim3(4, 256), 256>>>(vhi, vlo, wvhi, wvlo, bv,
        cat + 512,  cathi + 512,  catlo + 512,  V_DIM, CAT_K);
    mma_gemm<0><<<dim3(4, 256), 256>>>(lhi, llo, wlhi, wllo, bl,
        cat + 1024, cathi + 1024, catlo + 1024, L_DIM, CAT_K);

    // context = tanh(cat @ Wc^T + bc)
    mma_gemm<1><<<dim3(4, 256), 256>>>(cathi, catlo, wchi, wclo, bc,
        ctx, (u16*)nullptr, (u16*)nullptr, CAT_K, H_DIM);

    // attention softmax fusion -> fus hi/lo
    fusion_kernel<<<ROWS / 8, 256>>>();

    // xg = fusion @ Wih^T + (bih + bhh)
    mma_gemm<2><<<dim3(16, 256), 256>>>(fushi, fuslo, wihhi, wihlo, bsum,
        xg, (u16*)nullptr, (u16*)nullptr, H_DIM, G4);

    // recurrent LSTM
    lstm_kernel<<<NCTA, 256>>>(h0, c0, Whh, out);
}

// round 8
// speedup vs baseline: 1.8990x; 1.0516x over previous
#include <cuda_runtime.h>
#include <cuda_bf16.h>
#include <cstdint>

typedef unsigned long long ull;
typedef unsigned short u16;
typedef unsigned int u32;

// ---------------- Problem constants ----------------
#define A_DIM 512
#define V_DIM 768
#define L_DIM 1024
#define H_DIM 512
#define BB    16
#define SS    2048
#define ROWS  (BB * SS)        // 32768
#define G4    (4 * H_DIM)      // 2048
#define CAT_K 1536

// ---------------- Scratch (device globals; no allocation allowed) ----------------
__device__ float g_cat[(size_t)ROWS * CAT_K];
__device__ float g_ctx[(size_t)ROWS * H_DIM];
__device__ float g_xg [(size_t)ROWS * G4];
__device__ float g_hbuf[2 * BB * H_DIM];
__device__ float g_bsum[G4];
__device__ unsigned int g_ctr;

__device__ __align__(16) u16 g_ahi[(size_t)ROWS * A_DIM],  g_alo[(size_t)ROWS * A_DIM];
__device__ __align__(16) u16 g_vhi[(size_t)ROWS * V_DIM],  g_vlo[(size_t)ROWS * V_DIM];
__device__ __align__(16) u16 g_lhi[(size_t)ROWS * L_DIM],  g_llo[(size_t)ROWS * L_DIM];
__device__ __align__(16) u16 g_cathi[(size_t)ROWS * CAT_K], g_catlo[(size_t)ROWS * CAT_K];
__device__ __align__(16) u16 g_fushi[(size_t)ROWS * H_DIM], g_fuslo[(size_t)ROWS * H_DIM];
__device__ __align__(16) u16 g_wahi[H_DIM * A_DIM],  g_walo[H_DIM * A_DIM];
__device__ __align__(16) u16 g_wvhi[H_DIM * V_DIM],  g_wvlo[H_DIM * V_DIM];
__device__ __align__(16) u16 g_wlhi[H_DIM * L_DIM],  g_wllo[H_DIM * L_DIM];
__device__ __align__(16) u16 g_wchi[H_DIM * CAT_K],  g_wclo[H_DIM * CAT_K];
__device__ __align__(16) u16 g_wihhi[G4 * H_DIM],    g_wihlo[G4 * H_DIM];

// ---------------- helpers ----------------
__device__ __forceinline__ ull ffma2(ull a, ull b, ull c) {
    asm("fma.rn.f32x2 %0, %1, %2, %0;" : "+l"(c) : "l"(a), "l"(b));
    return c;
}
__device__ __forceinline__ void unpack2(ull v, float& x, float& y) {
    asm("mov.b64 {%0, %1}, %2;" : "=f"(x), "=f"(y) : "l"(v));
}
__device__ __forceinline__ float sigmf(float x) { return 1.0f / (1.0f + __expf(-x)); }

__device__ __forceinline__ u32 smem_u32(const void* p) {
    u32 a;
    asm("{ .reg .u64 t; cvta.to.shared.u64 t, %1; cvt.u32.u64 %0, t; }" : "=r"(a) : "l"(p));
    return a;
}

#define SWZ128(x) ((x) ^ (((x) >> 3) & 0x70))

__device__ __forceinline__ void ldsm4(u32& r0, u32& r1, u32& r2, u32& r3, u32 addr) {
    asm volatile("ldmatrix.sync.aligned.m8n8.x4.shared.b16 {%0,%1,%2,%3}, [%4];"
        : "=r"(r0), "=r"(r1), "=r"(r2), "=r"(r3) : "r"(addr));
}
__device__ __forceinline__ void mma16816(float* c, u32 a0, u32 a1, u32 a2, u32 a3,
                                         u32 b0, u32 b1) {
    asm volatile("mma.sync.aligned.m16n8k16.row.col.f32.bf16.bf16.f32 "
        "{%0,%1,%2,%3}, {%4,%5,%6,%7}, {%8,%9}, {%0,%1,%2,%3};"
        : "+f"(c[0]), "+f"(c[1]), "+f"(c[2]), "+f"(c[3])
        : "r"(a0), "r"(a1), "r"(a2), "r"(a3), "r"(b0), "r"(b1));
}
__device__ __forceinline__ void cp16(u32 saddr, const void* g) {
    asm volatile("cp.async.cg.shared.global [%0], [%1], 16;" :: "r"(saddr), "l"(g));
}

// ---------------- Init ----------------
__global__ void init_kernel(const float* __restrict__ bih, const float* __restrict__ bhh) {
    int i = blockIdx.x * blockDim.x + threadIdx.x;
    if (i < G4) g_bsum[i] = bih[i] + bhh[i];
    if (i == 0) g_ctr = 0u;
}

// ---------------- fp32 -> bf16 hi/lo split (vectorized x4) ----------------
__global__ void split_kernel(const float* __restrict__ s, u16* __restrict__ hi,
                             u16* __restrict__ lo, int n4) {
    int i = blockIdx.x * blockDim.x + threadIdx.x;
    if (i < n4) {
        float4 x = ((const float4*)s)[i];
        float xs[4] = { x.x, x.y, x.z, x.w };
        u32 hp[2], lp[2];
#pragma unroll
        for (int q = 0; q < 2; q++) {
            __nv_bfloat16 h0 = __float2bfloat16(xs[2 * q]);
            __nv_bfloat16 h1 = __float2bfloat16(xs[2 * q + 1]);
            float r0 = xs[2 * q]     - __bfloat162float(h0);
            float r1 = xs[2 * q + 1] - __bfloat162float(h1);
            __nv_bfloat16 l0 = __float2bfloat16(r0);
            __nv_bfloat16 l1 = __float2bfloat16(r1);
            hp[q] = (u32)*(u16*)&h0 | ((u32)*(u16*)&h1 << 16);
            lp[q] = (u32)*(u16*)&l0 | ((u32)*(u16*)&l1 << 16);
        }
        ((uint2*)hi)[i] = make_uint2(hp[0], hp[1]);
        ((uint2*)lo)[i] = make_uint2(lp[0], lp[1]);
    }
}

// ---------------- pipelined mma.sync GEMM ----------------
// C[M,N] = X[M,K] @ W[N,K]^T + bias ; bf16 split 3-pass fp32 accum.
// BM=BN=128, BK=64 (SW128 128B rows), 256 threads = 8 warps (4m x 2n).
// 3-stage cp.async pipeline; one __syncthreads per chunk.
#define STAGES 3
#define STG_BYTES 32768                     // 16KB A + 16KB B
#define GSMEM_BYTES (STAGES * STG_BYTES)    // 96KB

template<int MODE>
__global__ __launch_bounds__(256, 2)
void mma_gemm(const u16* __restrict__ Xhi, const u16* __restrict__ Xlo,
              const u16* __restrict__ Whi, const u16* __restrict__ Wlo,
              const float* __restrict__ bias, float* __restrict__ Cf,
              u16* __restrict__ Chi, u16* __restrict__ Clo,
              int K, int ldc)
{
    extern __shared__ __align__(16) char smem[];
    const u32 sbase = smem_u32(smem);

    const int tid  = threadIdx.x;
    const int lane = tid & 31;
    const int w    = tid >> 5;
    const int wm   = w & 3;
    const int wn   = w >> 2;
    const int m0 = blockIdx.y * 128;
    const int n0 = blockIdx.x * 128;

    float acc[2][8][4];
#pragma unroll
    for (int i = 0; i < 2; i++)
#pragma unroll
        for (int j = 0; j < 8; j++)
#pragma unroll
            for (int q = 0; q < 4; q++) acc[i][j][q] = 0.f;

    // ldmatrix lane addressing
    const int a_row = wm * 32 + (lane & 15);
    const int a_kb  = (lane >> 4) * 16;
    const int b_row = wn * 64 + (lane & 7) + ((lane >> 4) << 3);
    const int b_kb  = ((lane >> 3) & 1) * 16;

    // loader lane addressing: 4 chunks of 16B per thread per tile
    const int ld_row = tid >> 3;       // +128*i rows handled by i loop? no: id=tid+256i
    const int ld_c   = tid & 7;
    (void)ld_row; (void)ld_c;

    const u16* Xs[3] = { Xhi, Xhi, Xlo };
    const u16* Ws[3] = { Whi, Wlo, Whi };
    const int KP = K / 64;
    const int NC = 3 * KP;

    auto issue = [&](int ch) {
        if (ch < NC) {
            const int pass = ch / KP, kk = ch % KP;
            const u16* Ap = Xs[pass] + (size_t)m0 * K + kk * 64;
            const u16* Bp = Ws[pass] + (size_t)n0 * K + kk * 64;
            const u32 sA = sbase + (ch % STAGES) * STG_BYTES;
            const u32 sB = sA + 16384;
#pragma unroll
            for (int i = 0; i < 4; i++) {
                const int id  = tid + 256 * i;
                const int row = id >> 3;
                const int c   = id & 7;
                const u32 off = SWZ128(row * 128 + c * 16);
                cp16(sA + off, Ap + (size_t)row * K + c * 8);
                cp16(sB + off, Bp + (size_t)row * K + c * 8);
            }
        }
        asm volatile("cp.async.commit_group;");
    };

    issue(0);
    issue(1);

    for (int ch = 0; ch < NC; ch++) {
        asm volatile("cp.async.wait_group 1;");
        __syncthreads();
        issue(ch + 2);

        const u32 sA = sbase + (ch % STAGES) * STG_BYTES;
        const u32 sB = sA + 16384;

#pragma unroll
        for (int ks = 0; ks < 4; ks++) {
            const int kb = ks * 32;
            u32 a[2][4];
#pragma unroll
            for (int mt = 0; mt < 2; mt++) {
                const u32 addr = sA + SWZ128((a_row + mt * 16) * 128 + a_kb + kb);
                ldsm4(a[mt][0], a[mt][1], a[mt][2], a[mt][3], addr);
            }
#pragma unroll
            for (int nt = 0; nt < 4; nt++) {
                u32 b0, b1, b2, b3;
                const u32 addr = sB + SWZ128((b_row + nt * 16) * 128 + b_kb + kb);
                ldsm4(b0, b1, b2, b3, addr);
#pragma unroll
                for (int mt = 0; mt < 2; mt++) {
                    mma16816(acc[mt][2 * nt],     a[mt][0], a[mt][1], a[mt][2], a[mt][3], b0, b1);
                    mma16816(acc[mt][2 * nt + 1], a[mt][0], a[mt][1], a[mt][2], a[mt][3], b2, b3);
                }
            }
        }
    }

    // epilogue
    const int mb = m0 + wm * 32 + (lane >> 2);
    const int nb = n0 + wn * 64 + (lane & 3) * 2;
#pragma unroll
    for (int mt = 0; mt < 2; mt++) {
#pragma unroll
        for (int nt = 0; nt < 8; nt++) {
            const int n = nb + nt * 8;
            const float b0 = bias[n], b1 = bias[n + 1];
#pragma unroll
            for (int h = 0; h < 2; h++) {
                const int m = mb + mt * 16 + h * 8;
                float v0 = acc[mt][nt][2 * h]     + b0;
                float v1 = acc[mt][nt][2 * h + 1] + b1;
                if (MODE == 1) { v0 = tanhf(v0); v1 = tanhf(v1); }
                *(float2*)&Cf[(size_t)m * ldc + n] = make_float2(v0, v1);
                if (MODE == 0) {
                    __nv_bfloat16 h0 = __float2bfloat16(v0);
                    __nv_bfloat16 h1 = __float2bfloat16(v1);
                    float r0 = v0 - __bfloat162float(h0);
                    float r1 = v1 - __bfloat162float(h1);
                    __nv_bfloat16 l0 = __float2bfloat16(r0);
                    __nv_bfloat16 l1 = __float2bfloat16(r1);
                    u32 hp = (u32)*(u16*)&h0 | ((u32)*(u16*)&h1 << 16);
                    u32 lp = (u32)*(u16*)&l0 | ((u32)*(u16*)&l1 << 16);
                    *(u32*)&Chi[(size_t)m * ldc + n] = hp;
                    *(u32*)&Clo[(size_t)m * ldc + n] = lp;
                }
            }
        }
    }
}

// ---------------- Attention fusion -> bf16 hi/lo fusion ----------------
__global__ __launch_bounds__(256)
void fusion_kernel()
{
    const int warp = threadIdx.x >> 5;
    const int lane = threadIdx.x & 31;
    const int row  = blockIdx.x * 8 + warp;

    const float* crow = g_cat + (size_t)row * CAT_K;
    const float* xrow = g_ctx + (size_t)row * H_DIM;

    float av[16], vv[16], lv[16];
    float sa = 0.f, sv = 0.f, sl = 0.f;
#pragma unroll
    for (int q = 0; q < 16; q++) {
        const int k = lane + 32 * q;
        const float c = xrow[k];
        av[q] = crow[k];
        vv[q] = crow[512 + k];
        lv[q] = crow[1024 + k];
        sa = fmaf(av[q], c, sa);
        sv = fmaf(vv[q], c, sv);
        sl = fmaf(lv[q], c, sl);
    }
#pragma unroll
    for (int m = 16; m >= 1; m >>= 1) {
        sa += __shfl_xor_sync(0xffffffffu, sa, m);
        sv += __shfl_xor_sync(0xffffffffu, sv, m);
        sl += __shfl_xor_sync(0xffffffffu, sl, m);
    }
    const float mx = fmaxf(sa, fmaxf(sv, sl));
    const float ea = __expf(sa - mx);
    const float ev = __expf(sv - mx);
    const float el = __expf(sl - mx);
    const float inv = 1.0f / (ea + ev + el);
    const float wa = ea * inv, wv = ev * inv, wl = el * inv;

    u16* fh = g_fushi + (size_t)row * H_DIM;
    u16* fl = g_fuslo + (size_t)row * H_DIM;
#pragma unroll
    for (int q = 0; q < 16; q++) {
        const int k = lane + 32 * q;
        const float v = wa * av[q] + wv * vv[q] + wl * lv[q];
        __nv_bfloat16 h = __float2bfloat16(v);
        float rr = v - __bfloat162float(h);
        __nv_bfloat16 l = __float2bfloat16(rr);
        fh[k] = *(u16*)&h;
        fl[k] = *(u16*)&l;
    }
}

// ---------------- Persistent LSTM (unchanged) ----------------
#define NCTA 128
#define OFF_R ((size_t)BB * SS * H_DIM)

__global__ __launch_bounds__(256, 1)
void lstm_kernel(const float* __restrict__ h0, const float* __restrict__ c0,
                 const float* __restrict__ Whh, float* __restrict__ out)
{
    __shared__ __align__(16) float h_s[BB * H_DIM];
    __shared__ float gates_s[4][4][BB];

    const int tid   = threadIdx.x;
    const int w     = tid >> 5;
    const int lane  = tid & 31;
    const int c     = blockIdx.x;
    const int gpair = w >> 2;
    const int bq    = w & 3;

    ull wgt[8][8];
#pragma unroll
    for (int r = 0; r < 8; r++) {
        const int gate = 2 * gpair + (r >> 2);
        const int j    = r & 3;
        const float* wr = Whh + (size_t)(gate * H_DIM + 4 * c + j) * H_DIM;
#pragma unroll
        for (int ic = 0; ic < 4; ic++) {
            ulonglong2 u = *(const ulonglong2*)(wr + 4 * lane + 128 * ic);
            wgt[r][2 * ic]     = u.x;
            wgt[r][2 * ic + 1] = u.y;
        }
    }

    const int jn = tid >> 4;
    const int b  = tid & 15;
    float c_val = 0.f;
    if (tid < 64) c_val = c0[b * H_DIM + 4 * c + jn];

    for (int t = 0; t < SS; t++) {
        float xv0 = 0.f, xv1 = 0.f, xv2 = 0.f, xv3 = 0.f;
        if (tid < 64) {
            const float* xr = g_xg + ((size_t)(b * SS + t)) * G4 + 4 * c + jn;
            xv0 = xr[0 * H_DIM];
            xv1 = xr[1 * H_DIM];
            xv2 = xr[2 * H_DIM];
            xv3 = xr[3 * H_DIM];
        }

        if (t > 0) {
            if (tid == 0) {
                const unsigned target = (unsigned)NCTA * (unsigned)t;
                while (*(volatile unsigned*)&g_ctr < target) {}
                __threadfence();
            }
            __syncthreads();
        }

        {
            const float* hsrc = (t == 0) ? h0 : (g_hbuf + (size_t)(t & 1) * (BB * H_DIM));
#pragma unroll
            for (int q = 0; q < 8; q++)
                ((float4*)h_s)[tid + 256 * q] = ((const float4*)hsrc)[tid + 256 * q];
        }
        __syncthreads();

#pragma unroll
        for (int bi = 0; bi < 4; bi++) {
            const int bb = 4 * bq + bi;
            ull hv[8];
#pragma unroll
            for (int ic = 0; ic < 4; ic++) {
                ulonglong2 u = *(const ulonglong2*)&h_s[bb * H_DIM + 4 * lane + 128 * ic];
                hv[2 * ic]     = u.x;
                hv[2 * ic + 1] = u.y;
            }
            ull acc[8];
#pragma unroll
            for (int r = 0; r < 8; r++) acc[r] = 0ull;
#pragma unroll
            for (int kq = 0; kq < 8; kq++)
#pragma unroll
                for (int r = 0; r < 8; r++)
                    acc[r] = ffma2(wgt[r][kq], hv[kq], acc[r]);
#pragma unroll
            for (int r = 0; r < 8; r++) {
                float x, y;
                unpack2(acc[r], x, y);
                float s = x + y;
                s += __shfl_xor_sync(0xffffffffu, s, 16);
                s += __shfl_xor_sync(0xffffffffu, s, 8);
                s += __shfl_xor_sync(0xffffffffu, s, 4);
                s += __shfl_xor_sync(0xffffffffu, s, 2);
                s += __shfl_xor_sync(0xffffffffu, s, 1);
                if (lane == r) gates_s[2 * gpair + (r >> 2)][r & 3][bb] = s;
            }
        }
        __syncthreads();

        if (tid < 64) {
            const float gi = gates_s[0][jn][b] + xv0;
            const float gf = gates_s[1][jn][b] + xv1;
            const float gg = gates_s[2][jn][b] + xv2;
            const float go = gates_s[3][jn][b] + xv3;
            const float iv = sigmf(gi);
            const float fv = sigmf(gf);
            const float gv = tanhf(gg);
            const float ov = sigmf(go);
            c_val = fv * c_val + iv * gv;
            const float h = ov * tanhf(c_val);
            const int col = 4 * c + jn;
            g_hbuf[(size_t)((t + 1) & 1) * (BB * H_DIM) + b * H_DIM + col] = h;
            out[((size_t)(b * SS + t)) * H_DIM + col] = h;
            if (t == SS - 1) {
                out[OFF_R + b * H_DIM + col]              = h;
                out[OFF_R + BB * H_DIM + b * H_DIM + col] = c_val;
            }
        }
        __threadfence();
        __syncthreads();
        if (tid == 0) atomicAdd(&g_ctr, 1u);
    }
}

// ---------------- Launch ----------------
extern "C" void kernel_launch(void* const* d_in, const int* in_sizes, int n_in,
                              void* d_out, int out_size)
{
    const float* a_in = (const float*)d_in[0];
    const float* v_in = (const float*)d_in[1];
    const float* l_in = (const float*)d_in[2];
    const float* h0   = (const float*)d_in[3];
    const float* c0   = (const float*)d_in[4];
    const float* Wa   = (const float*)d_in[5];
    const float* ba   = (const float*)d_in[6];
    const float* Wv   = (const float*)d_in[7];
    const float* bv   = (const float*)d_in[8];
    const float* Wl   = (const float*)d_in[9];
    const float* bl   = (const float*)d_in[10];
    const float* Wc   = (const float*)d_in[11];
    const float* bc   = (const float*)d_in[12];
    const float* Wih  = (const float*)d_in[13];
    const float* Whh  = (const float*)d_in[14];
    const float* bih  = (const float*)d_in[15];
    const float* bhh  = (const float*)d_in[16];
    float* out = (float*)d_out;

    float *cat, *ctx, *xg, *bsum;
    cudaGetSymbolAddress((void**)&cat,  g_cat);
    cudaGetSymbolAddress((void**)&ctx,  g_ctx);
    cudaGetSymbolAddress((void**)&xg,   g_xg);
    cudaGetSymbolAddress((void**)&bsum, g_bsum);
    u16 *ahi,*alo,*vhi,*vlo,*lhi,*llo,*cathi,*catlo,*fushi,*fuslo;
    u16 *wahi,*walo,*wvhi,*wvlo,*wlhi,*wllo,*wchi,*wclo,*wihhi,*wihlo;
    cudaGetSymbolAddress((void**)&ahi, g_ahi);   cudaGetSymbolAddress((void**)&alo, g_alo);
    cudaGetSymbolAddress((void**)&vhi, g_vhi);   cudaGetSymbolAddress((void**)&vlo, g_vlo);
    cudaGetSymbolAddress((void**)&lhi, g_lhi);   cudaGetSymbolAddress((void**)&llo, g_llo);
    cudaGetSymbolAddress((void**)&cathi, g_cathi); cudaGetSymbolAddress((void**)&catlo, g_catlo);
    cudaGetSymbolAddress((void**)&fushi, g_fushi); cudaGetSymbolAddress((void**)&fuslo, g_fuslo);
    cudaGetSymbolAddress((void**)&wahi, g_wahi); cudaGetSymbolAddress((void**)&walo, g_walo);
    cudaGetSymbolAddress((void**)&wvhi, g_wvhi); cudaGetSymbolAddress((void**)&wvlo, g_wvlo);
    cudaGetSymbolAddress((void**)&wlhi, g_wlhi); cudaGetSymbolAddress((void**)&wllo, g_wllo);
    cudaGetSymbolAddress((void**)&wchi, g_wchi); cudaGetSymbolAddress((void**)&wclo, g_wclo);
    cudaGetSymbolAddress((void**)&wihhi, g_wihhi); cudaGetSymbolAddress((void**)&wihlo, g_wihlo);

    cudaFuncSetAttribute(mma_gemm<0>, cudaFuncAttributeMaxDynamicSharedMemorySize, GSMEM_BYTES);
    cudaFuncSetAttribute(mma_gemm<1>, cudaFuncAttributeMaxDynamicSharedMemorySize, GSMEM_BYTES);
    cudaFuncSetAttribute(mma_gemm<2>, cudaFuncAttributeMaxDynamicSharedMemorySize, GSMEM_BYTES);

    init_kernel<<<2, 1024>>>(bih, bhh);

    auto SPLIT = [&](const float* s, u16* h, u16* l, int n) {
        split_kernel<<<(n / 4 + 255) / 256, 256>>>(s, h, l, n / 4);
    };
    SPLIT(a_in, ahi, alo, ROWS * A_DIM);
    SPLIT(v_in, vhi, vlo, ROWS * V_DIM);
    SPLIT(l_in, lhi, llo, ROWS * L_DIM);
    SPLIT(Wa, wahi, walo, H_DIM * A_DIM);
    SPLIT(Wv, wvhi, wvlo, H_DIM * V_DIM);
    SPLIT(Wl, wlhi, wllo, H_DIM * L_DIM);
    SPLIT(Wc, wchi, wclo, H_DIM * CAT_K);
    SPLIT(Wih, wihhi, wihlo, G4 * H_DIM);

    // projections -> cat fp32 + cat hi/lo (row stride 1536)
    mma_gemm<0><<<dim3(4, 256), 256, GSMEM_BYTES>>>(ahi, alo, wahi, walo, ba,
        cat,        cathi,        catlo,        A_DIM, CAT_K);
    mma_gemm<0><<<dim3(4, 256), 256, GSMEM_BYTES>>>(vhi, vlo, wvhi, wvlo, bv,
        cat + 512,  cathi + 512,  catlo + 512,  V_DIM, CAT_K);
    mma_gemm<0><<<dim3(4, 256), 256, GSMEM_BYTES>>>(lhi, llo, wlhi, wllo, bl,
        cat + 1024, cathi + 1024, catlo + 1024, L_DIM, CAT_K);

    // context = tanh(cat @ Wc^T + bc)
    mma_gemm<1><<<dim3(4, 256), 256, GSMEM_BYTES>>>(cathi, catlo, wchi, wclo, bc,
        ctx, (u16*)nullptr, (u16*)nullptr, CAT_K, H_DIM);

    // attention softmax fusion -> fus hi/lo
    fusion_kernel<<<ROWS / 8, 256>>>();

    // xg = fusion @ Wih^T + (bih + bhh)
    mma_gemm<2><<<dim3(16, 256), 256, GSMEM_BYTES>>>(fushi, fuslo, wihhi, wihlo, bsum,
        xg, (u16*)nullptr, (u16*)nullptr, H_DIM, G4);

    // recurrent LSTM
    lstm_kernel<<<NCTA, 256>>>(h0, c0, Whh, out);
}

// round 9
// speedup vs baseline: 1.9136x; 1.0077x over previous
#include <cuda_runtime.h>
#include <cuda_bf16.h>
#include <cstdint>

typedef unsigned long long ull;
typedef unsigned short u16;
typedef unsigned int u32;

// ---------------- Problem constants ----------------
#define A_DIM 512
#define V_DIM 768
#define L_DIM 1024
#define H_DIM 512
#define BB    16
#define SS    2048
#define ROWS  (BB * SS)        // 32768
#define G4    (4 * H_DIM)      // 2048
#define CAT_K 1536

// ---------------- Scratch (device globals; no allocation allowed) ----------------
__device__ float g_cat[(size_t)ROWS * CAT_K];
__device__ float g_ctx[(size_t)ROWS * H_DIM];
__device__ float g_xg [(size_t)ROWS * G4];
__device__ float g_hbuf[2 * BB * H_DIM];
__device__ float g_bsum[G4];
__device__ unsigned int g_ctr;

__device__ __align__(16) u16 g_ahi[(size_t)ROWS * A_DIM],  g_alo[(size_t)ROWS * A_DIM];
__device__ __align__(16) u16 g_vhi[(size_t)ROWS * V_DIM],  g_vlo[(size_t)ROWS * V_DIM];
__device__ __align__(16) u16 g_lhi[(size_t)ROWS * L_DIM],  g_llo[(size_t)ROWS * L_DIM];
__device__ __align__(16) u16 g_cathi[(size_t)ROWS * CAT_K], g_catlo[(size_t)ROWS * CAT_K];
__device__ __align__(16) u16 g_fushi[(size_t)ROWS * H_DIM], g_fuslo[(size_t)ROWS * H_DIM];
__device__ __align__(16) u16 g_wahi[H_DIM * A_DIM],  g_walo[H_DIM * A_DIM];
__device__ __align__(16) u16 g_wvhi[H_DIM * V_DIM],  g_wvlo[H_DIM * V_DIM];
__device__ __align__(16) u16 g_wlhi[H_DIM * L_DIM],  g_wllo[H_DIM * L_DIM];
__device__ __align__(16) u16 g_wchi[H_DIM * CAT_K],  g_wclo[H_DIM * CAT_K];
__device__ __align__(16) u16 g_wihhi[G4 * H_DIM],    g_wihlo[G4 * H_DIM];

// ---------------- helpers ----------------
__device__ __forceinline__ ull ffma2(ull a, ull b, ull c) {
    asm("fma.rn.f32x2 %0, %1, %2, %0;" : "+l"(c) : "l"(a), "l"(b));
    return c;
}
__device__ __forceinline__ void unpack2(ull v, float& x, float& y) {
    asm("mov.b64 {%0, %1}, %2;" : "=f"(x), "=f"(y) : "l"(v));
}
__device__ __forceinline__ float sigmf(float x) { return 1.0f / (1.0f + __expf(-x)); }

__device__ __forceinline__ u32 smem_u32(const void* p) {
    u32 a;
    asm("{ .reg .u64 t; cvta.to.shared.u64 t, %1; cvt.u32.u64 %0, t; }" : "=r"(a) : "l"(p));
    return a;
}

#define SWZ128(x) ((x) ^ (((x) >> 3) & 0x70))

__device__ __forceinline__ void ldsm4(u32& r0, u32& r1, u32& r2, u32& r3, u32 addr) {
    asm volatile("ldmatrix.sync.aligned.m8n8.x4.shared.b16 {%0,%1,%2,%3}, [%4];"
        : "=r"(r0), "=r"(r1), "=r"(r2), "=r"(r3) : "r"(addr));
}
__device__ __forceinline__ void mma16816(float* c, const u32* a, u32 b0, u32 b1) {
    asm volatile("mma.sync.aligned.m16n8k16.row.col.f32.bf16.bf16.f32 "
        "{%0,%1,%2,%3}, {%4,%5,%6,%7}, {%8,%9}, {%0,%1,%2,%3};"
        : "+f"(c[0]), "+f"(c[1]), "+f"(c[2]), "+f"(c[3])
        : "r"(a[0]), "r"(a[1]), "r"(a[2]), "r"(a[3]), "r"(b0), "r"(b1));
}
__device__ __forceinline__ void cp16(u32 saddr, const void* g) {
    asm volatile("cp.async.cg.shared.global [%0], [%1], 16;" :: "r"(saddr), "l"(g));
}

// ---------------- Init ----------------
__global__ void init_kernel(const float* __restrict__ bih, const float* __restrict__ bhh) {
    int i = blockIdx.x * blockDim.x + threadIdx.x;
    if (i < G4) g_bsum[i] = bih[i] + bhh[i];
    if (i == 0) g_ctr = 0u;
}

// ---------------- fp32 -> bf16 hi/lo splits (fused, vectorized) ----------------
__device__ __forceinline__ void split4(const float* __restrict__ s, u16* __restrict__ hi,
                                       u16* __restrict__ lo, size_t i) {
    float4 x = ((const float4*)s)[i];
    float xs[4] = { x.x, x.y, x.z, x.w };
    u32 hp[2], lp[2];
#pragma unroll
    for (int q = 0; q < 2; q++) {
        __nv_bfloat16 h0 = __float2bfloat16(xs[2 * q]);
        __nv_bfloat16 h1 = __float2bfloat16(xs[2 * q + 1]);
        float r0 = xs[2 * q]     - __bfloat162float(h0);
        float r1 = xs[2 * q + 1] - __bfloat162float(h1);
        __nv_bfloat16 l0 = __float2bfloat16(r0);
        __nv_bfloat16 l1 = __float2bfloat16(r1);
        hp[q] = (u32)*(u16*)&h0 | ((u32)*(u16*)&h1 << 16);
        lp[q] = (u32)*(u16*)&l0 | ((u32)*(u16*)&l1 << 16);
    }
    ((uint2*)hi)[i] = make_uint2(hp[0], hp[1]);
    ((uint2*)lo)[i] = make_uint2(lp[0], lp[1]);
}

__global__ void split_in_kernel(const float* __restrict__ a, const float* __restrict__ v,
                                const float* __restrict__ l) {
    const size_t i = (size_t)blockIdx.x * blockDim.x + threadIdx.x;
    const int seg = blockIdx.y;
    if (seg == 0) { if (i < (size_t)ROWS * A_DIM / 4) split4(a, g_ahi, g_alo, i); }
    else if (seg == 1) { if (i < (size_t)ROWS * V_DIM / 4) split4(v, g_vhi, g_vlo, i); }
    else { split4(l, g_lhi, g_llo, i); }
}

__global__ void split_w_kernel(const float* __restrict__ wa, const float* __restrict__ wv,
                               const float* __restrict__ wl, const float* __restrict__ wc,
                               const float* __restrict__ wih) {
    const size_t i = (size_t)blockIdx.x * blockDim.x + threadIdx.x;
    const int seg = blockIdx.y;
    if (seg == 0)      { if (i < (size_t)H_DIM * A_DIM / 4) split4(wa, g_wahi, g_walo, i); }
    else if (seg == 1) { if (i < (size_t)H_DIM * V_DIM / 4) split4(wv, g_wvhi, g_wvlo, i); }
    else if (seg == 2) { if (i < (size_t)H_DIM * L_DIM / 4) split4(wl, g_wlhi, g_wllo, i); }
    else if (seg == 3) { if (i < (size_t)H_DIM * CAT_K / 4) split4(wc, g_wchi, g_wclo, i); }
    else               { split4(wih, g_wihhi, g_wihlo, i); }
}

// ---------------- merged-pass pipelined mma.sync GEMM ----------------
// C = Xhi@Whi^T + Xhi@Wlo^T + Xlo@Whi^T + bias, fp32 accum.
// Per BK=64 chunk: load Ahi|Alo|Bhi|Blo (64KB/stage), 3 stages, cp.async pipeline.
// BM=BN=128, 256 threads = 8 warps (4m x 2n), warp tile 32x64.
#define STAGES 3
#define TILE_B 16384
#define STG_BYTES (4 * TILE_B)              // 64KB
#define GSMEM_BYTES (STAGES * STG_BYTES)    // 192KB

template<int MODE>
__global__ __launch_bounds__(256, 1)
void mma_gemm(const u16* __restrict__ Xhi, const u16* __restrict__ Xlo,
              const u16* __restrict__ Whi, const u16* __restrict__ Wlo,
              const float* __restrict__ bias, float* __restrict__ Cf,
              u16* __restrict__ Chi, u16* __restrict__ Clo,
              int K, int ldc)
{
    extern __shared__ __align__(16) char smem[];
    const u32 sbase = smem_u32(smem);

    const int tid  = threadIdx.x;
    const int lane = tid & 31;
    const int w    = tid >> 5;
    const int wm   = w & 3;
    const int wn   = w >> 2;
    const int m0 = blockIdx.y * 128;
    const int n0 = blockIdx.x * 128;

    float acc[2][8][4];
#pragma unroll
    for (int i = 0; i < 2; i++)
#pragma unroll
        for (int j = 0; j < 8; j++)
#pragma unroll
            for (int q = 0; q < 4; q++) acc[i][j][q] = 0.f;

    // ldmatrix lane addressing
    const int a_row = wm * 32 + (lane & 15);
    const int a_kb  = (lane >> 4) * 16;
    const int b_row = wn * 64 + (lane & 7) + ((lane >> 4) << 3);
    const int b_kb  = ((lane >> 3) & 1) * 16;

    const int KP = K / 64;

    auto issue = [&](int ch) {
        if (ch < KP) {
            const int kk = ch;
            const u16* A0 = Xhi + (size_t)m0 * K + kk * 64;
            const u16* A1 = Xlo + (size_t)m0 * K + kk * 64;
            const u16* B0 = Whi + (size_t)n0 * K + kk * 64;
            const u16* B1 = Wlo + (size_t)n0 * K + kk * 64;
            const u32 st = sbase + (ch % STAGES) * STG_BYTES;
#pragma unroll
            for (int i = 0; i < 4; i++) {
                const int id  = tid + 256 * i;
                const int row = id >> 3;
                const int c   = id & 7;
                const u32 off = SWZ128(row * 128 + c * 16);
                const size_t g = (size_t)row * K + c * 8;
                cp16(st + 0 * TILE_B + off, A0 + g);
                cp16(st + 1 * TILE_B + off, A1 + g);
                cp16(st + 2 * TILE_B + off, B0 + g);
                cp16(st + 3 * TILE_B + off, B1 + g);
            }
        }
        asm volatile("cp.async.commit_group;");
    };

    issue(0);
    issue(1);

    for (int ch = 0; ch < KP; ch++) {
        asm volatile("cp.async.wait_group 1;");
        __syncthreads();
        issue(ch + 2);

        const u32 st = sbase + (ch % STAGES) * STG_BYTES;
        const u32 sAh = st, sAl = st + TILE_B, sBh = st + 2 * TILE_B, sBl = st + 3 * TILE_B;

#pragma unroll
        for (int ks = 0; ks < 4; ks++) {
            const int kb = ks * 32;
            u32 ah[2][4], al[2][4];
#pragma unroll
            for (int mt = 0; mt < 2; mt++) {
                const u32 ao = SWZ128((a_row + mt * 16) * 128 + a_kb + kb);
                ldsm4(ah[mt][0], ah[mt][1], ah[mt][2], ah[mt][3], sAh + ao);
                ldsm4(al[mt][0], al[mt][1], al[mt][2], al[mt][3], sAl + ao);
            }
#pragma unroll
            for (int nt = 0; nt < 4; nt++) {
                const u32 bo = SWZ128((b_row + nt * 16) * 128 + b_kb + kb);
                u32 bh0, bh1, bh2, bh3, bl0, bl1, bl2, bl3;
                ldsm4(bh0, bh1, bh2, bh3, sBh + bo);
                ldsm4(bl0, bl1, bl2, bl3, sBl + bo);
#pragma unroll
                for (int mt = 0; mt < 2; mt++) {
                    mma16816(acc[mt][2 * nt],     ah[mt], bh0, bh1);
                    mma16816(acc[mt][2 * nt + 1], ah[mt], bh2, bh3);
                    mma16816(acc[mt][2 * nt],     ah[mt], bl0, bl1);
                    mma16816(acc[mt][2 * nt + 1], ah[mt], bl2, bl3);
                    mma16816(acc[mt][2 * nt],     al[mt], bh0, bh1);
                    mma16816(acc[mt][2 * nt + 1], al[mt], bh2, bh3);
                }
            }
        }
    }

    // epilogue
    const int mb = m0 + wm * 32 + (lane >> 2);
    const int nb = n0 + wn * 64 + (lane & 3) * 2;
#pragma unroll
    for (int mt = 0; mt < 2; mt++) {
#pragma unroll
        for (int nt = 0; nt < 8; nt++) {
            const int n = nb + nt * 8;
            const float b0 = bias[n], b1 = bias[n + 1];
#pragma unroll
            for (int h = 0; h < 2; h++) {
                const int m = mb + mt * 16 + h * 8;
                float v0 = acc[mt][nt][2 * h]     + b0;
                float v1 = acc[mt][nt][2 * h + 1] + b1;
                if (MODE == 1) { v0 = tanhf(v0); v1 = tanhf(v1); }
                *(float2*)&Cf[(size_t)m * ldc + n] = make_float2(v0, v1);
                if (MODE == 0) {
                    __nv_bfloat16 h0 = __float2bfloat16(v0);
                    __nv_bfloat16 h1 = __float2bfloat16(v1);
                    float r0 = v0 - __bfloat162float(h0);
                    float r1 = v1 - __bfloat162float(h1);
                    __nv_bfloat16 l0 = __float2bfloat16(r0);
                    __nv_bfloat16 l1 = __float2bfloat16(r1);
                    u32 hp = (u32)*(u16*)&h0 | ((u32)*(u16*)&h1 << 16);
                    u32 lp = (u32)*(u16*)&l0 | ((u32)*(u16*)&l1 << 16);
                    *(u32*)&Chi[(size_t)m * ldc + n] = hp;
                    *(u32*)&Clo[(size_t)m * ldc + n] = lp;
                }
            }
        }
    }
}

// ---------------- Attention fusion -> bf16 hi/lo fusion ----------------
__global__ __launch_bounds__(256)
void fusion_kernel()
{
    const int warp = threadIdx.x >> 5;
    const int lane = threadIdx.x & 31;
    const int row  = blockIdx.x * 8 + warp;

    const float* crow = g_cat + (size_t)row * CAT_K;
    const float* xrow = g_ctx + (size_t)row * H_DIM;

    float av[16], vv[16], lv[16];
    float sa = 0.f, sv = 0.f, sl = 0.f;
#pragma unroll
    for (int q = 0; q < 16; q++) {
        const int k = lane + 32 * q;
        const float c = xrow[k];
        av[q] = crow[k];
        vv[q] = crow[512 + k];
        lv[q] = crow[1024 + k];
        sa = fmaf(av[q], c, sa);
        sv = fmaf(vv[q], c, sv);
        sl = fmaf(lv[q], c, sl);
    }
#pragma unroll
    for (int m = 16; m >= 1; m >>= 1) {
        sa += __shfl_xor_sync(0xffffffffu, sa, m);
        sv += __shfl_xor_sync(0xffffffffu, sv, m);
        sl += __shfl_xor_sync(0xffffffffu, sl, m);
    }
    const float mx = fmaxf(sa, fmaxf(sv, sl));
    const float ea = __expf(sa - mx);
    const float ev = __expf(sv - mx);
    const float el = __expf(sl - mx);
    const float inv = 1.0f / (ea + ev + el);
    const float wa = ea * inv, wv = ev * inv, wl = el * inv;

    u16* fh = g_fushi + (size_t)row * H_DIM;
    u16* fl = g_fuslo + (size_t)row * H_DIM;
#pragma unroll
    for (int q = 0; q < 16; q++) {
        const int k = lane + 32 * q;
        const float v = wa * av[q] + wv * vv[q] + wl * lv[q];
        __nv_bfloat16 h = __float2bfloat16(v);
        float rr = v - __bfloat162float(h);
        __nv_bfloat16 l = __float2bfloat16(rr);
        fh[k] = *(u16*)&h;
        fl[k] = *(u16*)&l;
    }
}

// ---------------- Persistent LSTM (unchanged) ----------------
#define NCTA 128
#define OFF_R ((size_t)BB * SS * H_DIM)

__global__ __launch_bounds__(256, 1)
void lstm_kernel(const float* __restrict__ h0, const float* __restrict__ c0,
                 const float* __restrict__ Whh, float* __restrict__ out)
{
    __shared__ __align__(16) float h_s[BB * H_DIM];
    __shared__ float gates_s[4][4][BB];

    const int tid   = threadIdx.x;
    const int w     = tid >> 5;
    const int lane  = tid & 31;
    const int c     = blockIdx.x;
    const int gpair = w >> 2;
    const int bq    = w & 3;

    ull wgt[8][8];
#pragma unroll
    for (int r = 0; r < 8; r++) {
        const int gate = 2 * gpair + (r >> 2);
        const int j    = r & 3;
        const float* wr = Whh + (size_t)(gate * H_DIM + 4 * c + j) * H_DIM;
#pragma unroll
        for (int ic = 0; ic < 4; ic++) {
            ulonglong2 u = *(const ulonglong2*)(wr + 4 * lane + 128 * ic);
            wgt[r][2 * ic]     = u.x;
            wgt[r][2 * ic + 1] = u.y;
        }
    }

    const int jn = tid >> 4;
    const int b  = tid & 15;
    float c_val = 0.f;
    if (tid < 64) c_val = c0[b * H_DIM + 4 * c + jn];

    for (int t = 0; t < SS; t++) {
        float xv0 = 0.f, xv1 = 0.f, xv2 = 0.f, xv3 = 0.f;
        if (tid < 64) {
            const float* xr = g_xg + ((size_t)(b * SS + t)) * G4 + 4 * c + jn;
            xv0 = xr[0 * H_DIM];
            xv1 = xr[1 * H_DIM];
            xv2 = xr[2 * H_DIM];
            xv3 = xr[3 * H_DIM];
        }

        if (t > 0) {
            if (tid == 0) {
                const unsigned target = (unsigned)NCTA * (unsigned)t;
                while (*(volatile unsigned*)&g_ctr < target) {}
                __threadfence();
            }
            __syncthreads();
        }

        {
            const float* hsrc = (t == 0) ? h0 : (g_hbuf + (size_t)(t & 1) * (BB * H_DIM));
#pragma unroll
            for (int q = 0; q < 8; q++)
                ((float4*)h_s)[tid + 256 * q] = ((const float4*)hsrc)[tid + 256 * q];
        }
        __syncthreads();

#pragma unroll
        for (int bi = 0; bi < 4; bi++) {
            const int bb = 4 * bq + bi;
            ull hv[8];
#pragma unroll
            for (int ic = 0; ic < 4; ic++) {
                ulonglong2 u = *(const ulonglong2*)&h_s[bb * H_DIM + 4 * lane + 128 * ic];
                hv[2 * ic]     = u.x;
                hv[2 * ic + 1] = u.y;
            }
            ull acc[8];
#pragma unroll
            for (int r = 0; r < 8; r++) acc[r] = 0ull;
#pragma unroll
            for (int kq = 0; kq < 8; kq++)
#pragma unroll
                for (int r = 0; r < 8; r++)
                    acc[r] = ffma2(wgt[r][kq], hv[kq], acc[r]);
#pragma unroll
            for (int r = 0; r < 8; r++) {
                float x, y;
                unpack2(acc[r], x, y);
                float s = x + y;
                s += __shfl_xor_sync(0xffffffffu, s, 16);
                s += __shfl_xor_sync(0xffffffffu, s, 8);
                s += __shfl_xor_sync(0xffffffffu, s, 4);
                s += __shfl_xor_sync(0xffffffffu, s, 2);
                s += __shfl_xor_sync(0xffffffffu, s, 1);
                if (lane == r) gates_s[2 * gpair + (r >> 2)][r & 3][bb] = s;
            }
        }
        __syncthreads();

        if (tid < 64) {
            const float gi = gates_s[0][jn][b] + xv0;
            const float gf = gates_s[1][jn][b] + xv1;
            const float gg = gates_s[2][jn][b] + xv2;
            const float go = gates_s[3][jn][b] + xv3;
            const float iv = sigmf(gi);
            const float fv = sigmf(gf);
            const float gv = tanhf(gg);
            const float ov = sigmf(go);
            c_val = fv * c_val + iv * gv;
            const float h = ov * tanhf(c_val);
            const int col = 4 * c + jn;
            g_hbuf[(size_t)((t + 1) & 1) * (BB * H_DIM) + b * H_DIM + col] = h;
            out[((size_t)(b * SS + t)) * H_DIM + col] = h;
            if (t == SS - 1) {
                out[OFF_R + b * H_DIM + col]              = h;
                out[OFF_R + BB * H_DIM + b * H_DIM + col] = c_val;
            }
        }
        __threadfence();
        __syncthreads();
        if (tid == 0) atomicAdd(&g_ctr, 1u);
    }
}

// ---------------- Launch ----------------
extern "C" void kernel_launch(void* const* d_in, const int* in_sizes, int n_in,
                              void* d_out, int out_size)
{
    const float* a_in = (const float*)d_in[0];
    const float* v_in = (const float*)d_in[1];
    const float* l_in = (const float*)d_in[2];
    const float* h0   = (const float*)d_in[3];
    const float* c0   = (const float*)d_in[4];
    const float* Wa   = (const float*)d_in[5];
    const float* ba   = (const float*)d_in[6];
    const float* Wv   = (const float*)d_in[7];
    const float* bv   = (const float*)d_in[8];
    const float* Wl   = (const float*)d_in[9];
    const float* bl   = (const float*)d_in[10];
    const float* Wc   = (const float*)d_in[11];
    const float* bc   = (const float*)d_in[12];
    const float* Wih  = (const float*)d_in[13];
    const float* Whh  = (const float*)d_in[14];
    const float* bih  = (const float*)d_in[15];
    const float* bhh  = (const float*)d_in[16];
    float* out = (float*)d_out;

    float *cat, *ctx, *xg, *bsum;
    cudaGetSymbolAddress((void**)&cat,  g_cat);
    cudaGetSymbolAddress((void**)&ctx,  g_ctx);
    cudaGetSymbolAddress((void**)&xg,   g_xg);
    cudaGetSymbolAddress((void**)&bsum, g_bsum);
    u16 *ahi,*alo,*vhi,*vlo,*lhi,*llo,*cathi,*catlo,*fushi,*fuslo;
    u16 *wahi,*walo,*wvhi,*wvlo,*wlhi,*wllo,*wchi,*wclo,*wihhi,*wihlo;
    cudaGetSymbolAddress((void**)&ahi, g_ahi);   cudaGetSymbolAddress((void**)&alo, g_alo);
    cudaGetSymbolAddress((void**)&vhi, g_vhi);   cudaGetSymbolAddress((void**)&vlo, g_vlo);
    cudaGetSymbolAddress((void**)&lhi, g_lhi);   cudaGetSymbolAddress((void**)&llo, g_llo);
    cudaGetSymbolAddress((void**)&cathi, g_cathi); cudaGetSymbolAddress((void**)&catlo, g_catlo);
    cudaGetSymbolAddress((void**)&fushi, g_fushi); cudaGetSymbolAddress((void**)&fuslo, g_fuslo);
    cudaGetSymbolAddress((void**)&wahi, g_wahi); cudaGetSymbolAddress((void**)&walo, g_walo);
    cudaGetSymbolAddress((void**)&wvhi, g_wvhi); cudaGetSymbolAddress((void**)&wvlo, g_wvlo);
    cudaGetSymbolAddress((void**)&wlhi, g_wlhi); cudaGetSymbolAddress((void**)&wllo, g_wllo);
    cudaGetSymbolAddress((void**)&wchi, g_wchi); cudaGetSymbolAddress((void**)&wclo, g_wclo);
    cudaGetSymbolAddress((void**)&wihhi, g_wihhi); cudaGetSymbolAddress((void**)&wihlo, g_wihlo);

    cudaFuncSetAttribute(mma_gemm<0>, cudaFuncAttributeMaxDynamicSharedMemorySize, GSMEM_BYTES);
    cudaFuncSetAttribute(mma_gemm<1>, cudaFuncAttributeMaxDynamicSharedMemorySize, GSMEM_BYTES);
    cudaFuncSetAttribute(mma_gemm<2>, cudaFuncAttributeMaxDynamicSharedMemorySize, GSMEM_BYTES);

    // launch 0
    init_kernel<<<2, 1024>>>(bih, bhh);
    // launch 1: input splits (3 segments; grid sized for largest)
    split_in_kernel<<<dim3(32768, 3), 256>>>(a_in, v_in, l_in);
    // launch 2: weight splits (5 segments)
    split_w_kernel<<<dim3(1024, 5), 256>>>(Wa, Wv, Wl, Wc, Wih);

    // launches 3-5: projections -> cat fp32 + cat hi/lo (row stride 1536)
    mma_gemm<0><<<dim3(4, 256), 256, GSMEM_BYTES>>>(ahi, alo, wahi, walo, ba,
        cat,        cathi,        catlo,        A_DIM, CAT_K);
    mma_gemm<0><<<dim3(4, 256), 256, GSMEM_BYTES>>>(vhi, vlo, wvhi, wvlo, bv,
        cat + 512,  cathi + 512,  catlo + 512,  V_DIM, CAT_K);
    mma_gemm<0><<<dim3(4, 256), 256, GSMEM_BYTES>>>(lhi, llo, wlhi, wllo, bl,
        cat + 1024, cathi + 1024, catlo + 1024, L_DIM, CAT_K);   // <- ncu -s 5 target

    // context = tanh(cat @ Wc^T + bc)
    mma_gemm<1><<<dim3(4, 256), 256, GSMEM_BYTES>>>(cathi, catlo, wchi, wclo, bc,
        ctx, (u16*)nullptr, (u16*)nullptr, CAT_K, H_DIM);

    // attention softmax fusion -> fus hi/lo
    fusion_kernel<<<ROWS / 8, 256>>>();

    // xg = fusion @ Wih^T + (bih + bhh)
    mma_gemm<2><<<dim3(16, 256), 256, GSMEM_BYTES>>>(fushi, fuslo, wihhi, wihlo, bsum,
        xg, (u16*)nullptr, (u16*)nullptr, H_DIM, G4);

    // recurrent LSTM
    lstm_kernel<<<NCTA, 256>>>(h0, c0, Whh, out);
}